// round 10
// baseline (speedup 1.0000x reference)
#include <cuda_runtime.h>
#include <cuda_bf16.h>
#include <stdint.h>
#include <string.h>

// Problem constants
#define BDIM   1024
#define NSEQ   2304
#define NB     4
#define NH     16
#define HD     64
#define MROWS  (NB*NSEQ)      // 9216
#define HPATCH 48

// ---------------- scratch (static device globals; no allocation) -------------
__device__ float g_q [(size_t)NB*NH*NSEQ*HD];     // pre-rope  [b,h,n,d]
__device__ float g_k [(size_t)NB*NH*NSEQ*HD];
__device__ float g_v [(size_t)NB*NH*NSEQ*HD];
__device__ float g_q2[(size_t)NB*NH*NSEQ*HD];     // post-rope [b,h,n,d]
__device__ float g_k2[(size_t)NB*NH*NSEQ*HD];
__device__ float g_attn[(size_t)NB*NSEQ*BDIM];    // [b,n,D]

// ---------------- bf16 helpers -----------------------------------------------
__device__ __forceinline__ uint32_t pack2(float a, float b) {
    __nv_bfloat16 ha = __float2bfloat16_rn(a);
    __nv_bfloat16 hb = __float2bfloat16_rn(b);
    uint16_t ra, rb;
    memcpy(&ra, &ha, 2); memcpy(&rb, &hb, 2);
    return (uint32_t)ra | ((uint32_t)rb << 16);
}
__device__ __forceinline__ float lo_of(float x) {
    return x - __bfloat162float(__float2bfloat16_rn(x));
}
__device__ __forceinline__ float ex2_approx(float x) {
    float r;
    asm("ex2.approx.ftz.f32 %0, %1;" : "=f"(r) : "f"(x));
    return r;
}

__device__ __forceinline__ void mma_bf16(float acc[4],
    uint32_t a0, uint32_t a1, uint32_t a2, uint32_t a3,
    uint32_t b0, uint32_t b1)
{
    asm volatile(
        "mma.sync.aligned.m16n8k16.row.col.f32.bf16.bf16.f32 "
        "{%0,%1,%2,%3}, {%4,%5,%6,%7}, {%8,%9}, {%0,%1,%2,%3};"
        : "+f"(acc[0]), "+f"(acc[1]), "+f"(acc[2]), "+f"(acc[3])
        : "r"(a0), "r"(a1), "r"(a2), "r"(a3), "r"(b0), "r"(b1));
}

// =============================================================================
// Projection GEMM (bf16x3, DOUBLE-BUFFERED): C[m][n] = X[m]·W[n] + bias[n]
// 128x128 block, 256 threads, BK=32, warp tile 64x32. Two smem stages of
// 10240 words each (Xh/Xl/Wh/Wl @ 128 rows x 20-word stride, conflict-free).
// Per iter: prefetch LDG (next tile) -> 96 MMAs (current) -> convert+STS -> sync.
// Fragment maps / arithmetic / epilogue identical to the round-7 verified kernel.
// =============================================================================
#define PJ_STAGE 10240                  // words per stage
#define PJ_SMEM  (2*PJ_STAGE*4)         // 81920 bytes

template<int HEADSPLIT>
__global__ __launch_bounds__(256, 2)
void proj_mma3(const float* __restrict__ X, const float* __restrict__ W,
               const float* __restrict__ bias, float* __restrict__ out)
{
    extern __shared__ uint32_t dsm[];

    const int tid   = threadIdx.x;
    const int lane  = tid & 31;
    const int wid   = tid >> 5;
    const int warpM = wid & 1;
    const int warpN = wid >> 1;
    const int c     = lane & 3;
    const int lr    = lane >> 2;
    const int m0 = blockIdx.y * 128;
    const int n0 = blockIdx.x * 128;

    float acc[4][4][4];
    #pragma unroll
    for (int a = 0; a < 4; a++)
        #pragma unroll
        for (int b = 0; b < 4; b++)
            #pragma unroll
            for (int d = 0; d < 4; d++) acc[a][b][d] = 0.f;

    // ---- prologue: load tile 0 into stage 0
    {
        uint32_t* Xh32 = dsm;
        uint32_t* Xl32 = dsm + 2560;
        uint32_t* Wh32 = dsm + 5120;
        uint32_t* Wl32 = dsm + 7680;
        #pragma unroll
        for (int s = 0; s < 4; s++) {
            int idx = tid + s*256;            // 0..1023 float4 ids (128 x 8)
            int r   = idx >> 3;
            int kq  = (idx & 7) * 4;
            int w0  = r*20 + (kq >> 1);
            float4 xa = *(const float4*)&X[(size_t)(m0+r)*BDIM + kq];
            Xh32[w0    ] = pack2(xa.x, xa.y);
            Xh32[w0 + 1] = pack2(xa.z, xa.w);
            Xl32[w0    ] = pack2(lo_of(xa.x), lo_of(xa.y));
            Xl32[w0 + 1] = pack2(lo_of(xa.z), lo_of(xa.w));
            float4 wb = *(const float4*)&W[(size_t)(n0+r)*BDIM + kq];
            Wh32[w0    ] = pack2(wb.x, wb.y);
            Wh32[w0 + 1] = pack2(wb.z, wb.w);
            Wl32[w0    ] = pack2(lo_of(wb.x), lo_of(wb.y));
            Wl32[w0 + 1] = pack2(lo_of(wb.z), lo_of(wb.w));
        }
    }
    __syncthreads();

    for (int ktile = 0; ktile < 32; ktile++) {
        // ---- prefetch next tile into registers (latency hidden by MMAs below)
        float4 px[4], pw[4];
        if (ktile < 31) {
            const int k1 = (ktile + 1) * 32;
            #pragma unroll
            for (int s = 0; s < 4; s++) {
                int idx = tid + s*256;
                int r   = idx >> 3;
                int kq  = (idx & 7) * 4;
                px[s] = *(const float4*)&X[(size_t)(m0+r)*BDIM + k1 + kq];
                pw[s] = *(const float4*)&W[(size_t)(n0+r)*BDIM + k1 + kq];
            }
        }

        // ---- MMAs on current stage
        {
            uint32_t* Xh32 = dsm + (ktile & 1)*PJ_STAGE;
            uint32_t* Xl32 = Xh32 + 2560;
            uint32_t* Wh32 = Xh32 + 5120;
            uint32_t* Wl32 = Xh32 + 7680;
            #pragma unroll
            for (int kt = 0; kt < 2; kt++) {
                uint32_t ah[4][4], al[4][4];
                #pragma unroll
                for (int mt = 0; mt < 4; mt++) {
                    int rA = warpM*64 + mt*16 + lr;
                    int w  = rA*20 + kt*8 + c;
                    ah[mt][0] = Xh32[w];        ah[mt][1] = Xh32[w + 8*20];
                    ah[mt][2] = Xh32[w + 4];    ah[mt][3] = Xh32[w + 8*20 + 4];
                    al[mt][0] = Xl32[w];        al[mt][1] = Xl32[w + 8*20];
                    al[mt][2] = Xl32[w + 4];    al[mt][3] = Xl32[w + 8*20 + 4];
                }
                uint32_t bh[4][2], bl[4][2];
                #pragma unroll
                for (int nt = 0; nt < 4; nt++) {
                    int nB = warpN*32 + nt*8 + lr;
                    int w  = nB*20 + kt*8 + c;
                    bh[nt][0] = Wh32[w];  bh[nt][1] = Wh32[w + 4];
                    bl[nt][0] = Wl32[w];  bl[nt][1] = Wl32[w + 4];
                }
                #pragma unroll
                for (int mt = 0; mt < 4; mt++)
                    #pragma unroll
                    for (int nt = 0; nt < 4; nt++) {
                        mma_bf16(acc[mt][nt], ah[mt][0], ah[mt][1], ah[mt][2], ah[mt][3],
                                 bh[nt][0], bh[nt][1]);
                        mma_bf16(acc[mt][nt], ah[mt][0], ah[mt][1], ah[mt][2], ah[mt][3],
                                 bl[nt][0], bl[nt][1]);
                        mma_bf16(acc[mt][nt], al[mt][0], al[mt][1], al[mt][2], al[mt][3],
                                 bh[nt][0], bh[nt][1]);
                    }
            }
        }

        // ---- convert + store prefetched tile into the other stage
        if (ktile < 31) {
            uint32_t* Xh32 = dsm + ((ktile + 1) & 1)*PJ_STAGE;
            uint32_t* Xl32 = Xh32 + 2560;
            uint32_t* Wh32 = Xh32 + 5120;
            uint32_t* Wl32 = Xh32 + 7680;
            #pragma unroll
            for (int s = 0; s < 4; s++) {
                int idx = tid + s*256;
                int r   = idx >> 3;
                int kq  = (idx & 7) * 4;
                int w0  = r*20 + (kq >> 1);
                Xh32[w0    ] = pack2(px[s].x, px[s].y);
                Xh32[w0 + 1] = pack2(px[s].z, px[s].w);
                Xl32[w0    ] = pack2(lo_of(px[s].x), lo_of(px[s].y));
                Xl32[w0 + 1] = pack2(lo_of(px[s].z), lo_of(px[s].w));
                Wh32[w0    ] = pack2(pw[s].x, pw[s].y);
                Wh32[w0 + 1] = pack2(pw[s].z, pw[s].w);
                Wl32[w0    ] = pack2(lo_of(pw[s].x), lo_of(pw[s].y));
                Wl32[w0 + 1] = pack2(lo_of(pw[s].z), lo_of(pw[s].w));
            }
        }
        __syncthreads();
    }

    #pragma unroll
    for (int mt = 0; mt < 4; mt++) {
        int m = m0 + warpM*64 + mt*16 + lr;
        #pragma unroll
        for (int nt = 0; nt < 4; nt++) {
            int n = n0 + warpN*32 + nt*8 + 2*c;
            float b0v = __ldg(&bias[n]);
            float b1v = __ldg(&bias[n+1]);
            float v0 = acc[mt][nt][0] + b0v;
            float v1 = acc[mt][nt][1] + b1v;
            float v2 = acc[mt][nt][2] + b0v;
            float v3 = acc[mt][nt][3] + b1v;
            if (HEADSPLIT) {
                int b    = m / NSEQ;              // tile never crosses batch
                int nn   = m - b*NSEQ;
                int head = n >> 6;
                int hd0  = n & 63;
                size_t base = (((size_t)(b*NH + head))*NSEQ + nn)*HD + hd0;
                *(float2*)&out[base]        = make_float2(v0, v1);
                *(float2*)&out[base + 8*HD] = make_float2(v2, v3);  // m+8
            } else {
                *(float2*)&out[(size_t)m*BDIM + n]     = make_float2(v0, v1);
                *(float2*)&out[(size_t)(m+8)*BDIM + n] = make_float2(v2, v3);
            }
        }
    }
}

// =============================================================================
// 2D RoPE, out-of-place (verified round 4, kept verbatim).
// =============================================================================
__global__ void rope2_kernel(const float* __restrict__ src,
                             float* __restrict__ dst)
{
    const int total = NB*NH*NSEQ*32;
    int idx = blockIdx.x * blockDim.x + threadIdx.x;
    if (idx >= total) return;

    int j   = idx % 16;
    int r   = idx / 16;
    int seg = r % 2;
    int t   = r / 2;                 // (b*NH+h)*NSEQ + n
    int n   = t % NSEQ;
    int hpos = n / HPATCH;
    int wpos = n - hpos * HPATCH;

    float pos  = (seg == 0) ? (float)hpos : (float)wpos;
    float freq = powf(10000.0f, -(float)j / 16.0f);
    float ang  = pos * freq;
    float cc = cosf(ang);
    float ss = sinf(ang);

    size_t b0 = (size_t)t * HD + seg * 32 + j;
    float x1 = src[b0];
    float x2 = src[b0 + 16];
    dst[b0]      = x1 * cc - x2 * ss;
    dst[b0 + 16] = x1 * ss + x2 * cc;
}

// =============================================================================
// Flash attention (bf16x3 mma, log2-domain online softmax). VERBATIM round 7.
// =============================================================================
#define FW 36            // row stride in words for K / V^T / staged Q
#define QSC  0.18033688011112042f   // 0.125 * log2(e)

__global__ __launch_bounds__(256)
void flash_kernel()
{
    __shared__ __nv_bfloat16 smem[4 * 64 * 72];    // 36864 B
    __nv_bfloat16* Ksh = smem;                     // 64 rows * 72
    __nv_bfloat16* Ksl = Ksh + 64*72;
    __nv_bfloat16* Vsh = Ksl + 64*72;              // 64 d-rows * 72
    __nv_bfloat16* Vsl = Vsh + 64*72;
    uint32_t* Ksh32 = (uint32_t*)Ksh;  uint32_t* Ksl32 = (uint32_t*)Ksl;
    uint32_t* Vsh32 = (uint32_t*)Vsh;  uint32_t* Vsl32 = (uint32_t*)Vsl;

    const int tid  = threadIdx.x;
    const int lane = tid & 31;
    const int wid  = tid >> 5;
    const int c    = lane & 3;
    const int lr   = lane >> 2;
    const int q0   = blockIdx.x * 128;
    const int bh   = blockIdx.y;

    const float* qp = g_q2 + (size_t)bh * NSEQ * HD;
    const float* kp = g_k2 + (size_t)bh * NSEQ * HD;
    const float* vp = g_v  + (size_t)bh * NSEQ * HD;

    // ---- stage Q (hi in first half of smem, lo in second half), stride FW
    uint32_t* Qh32 = (uint32_t*)smem;              // 128*36 words = 18432 B
    uint32_t* Ql32 = Qh32 + 128*FW;                // next 18432 B
    #pragma unroll
    for (int s = 0; s < 8; s++) {
        int idx = tid + s*256;                 // 0..2047 float4 ids (128 x 16)
        int r   = idx >> 4;
        int dq  = (idx & 15) * 4;
        float4 qv = *(const float4*)&qp[(size_t)(q0+r)*HD + dq];
        int w0 = r*FW + (dq >> 1);
        Qh32[w0    ] = pack2(qv.x, qv.y);
        Qh32[w0 + 1] = pack2(qv.z, qv.w);
        Ql32[w0    ] = pack2(lo_of(qv.x), lo_of(qv.y));
        Ql32[w0 + 1] = pack2(lo_of(qv.z), lo_of(qv.w));
    }
    __syncthreads();

    // ---- load Q fragments (warp wid owns rows wid*16 .. +15)
    uint32_t qh[4][4], ql[4][4];
    {
        int rA = wid*16 + lr;
        #pragma unroll
        for (int kt = 0; kt < 4; kt++) {
            int w = rA*FW + kt*8 + c;
            qh[kt][0] = Qh32[w];      qh[kt][1] = Qh32[w + 8*FW];
            qh[kt][2] = Qh32[w + 4];  qh[kt][3] = Qh32[w + 8*FW + 4];
            ql[kt][0] = Ql32[w];      ql[kt][1] = Ql32[w + 8*FW];
            ql[kt][2] = Ql32[w + 4];  ql[kt][3] = Ql32[w + 8*FW + 4];
        }
    }
    __syncthreads();

    float m0r = -__int_as_float(0x7f800000), m1r = m0r;   // -inf (log2 units)
    float l0 = 0.f, l1 = 0.f;
    float O[8][4];
    #pragma unroll
    for (int dt = 0; dt < 8; dt++)
        #pragma unroll
        for (int j = 0; j < 4; j++) O[dt][j] = 0.f;

    for (int kv0 = 0; kv0 < NSEQ; kv0 += 64) {
        // ---- load K (row-major) and V (transposed), hi+lo splits
        #pragma unroll
        for (int s = 0; s < 4; s++) {
            int idx = tid + s*256;             // 0..1023 float4 ids (64 x 16)
            int kv  = idx >> 4;
            int dq  = (idx & 15) * 4;
            float4 kvv = *(const float4*)&kp[(size_t)(kv0+kv)*HD + dq];
            int w0 = kv*FW + (dq >> 1);
            Ksh32[w0    ] = pack2(kvv.x, kvv.y);
            Ksh32[w0 + 1] = pack2(kvv.z, kvv.w);
            Ksl32[w0    ] = pack2(lo_of(kvv.x), lo_of(kvv.y));
            Ksl32[w0 + 1] = pack2(lo_of(kvv.z), lo_of(kvv.w));
            float4 vv = *(const float4*)&vp[(size_t)(kv0+kv)*HD + dq];
            float vf[4] = {vv.x, vv.y, vv.z, vv.w};
            #pragma unroll
            for (int j = 0; j < 4; j++) {
                Vsh[(dq+j)*72 + kv] = __float2bfloat16_rn(vf[j]);
                Vsl[(dq+j)*72 + kv] = __float2bfloat16_rn(lo_of(vf[j]));
            }
        }
        __syncthreads();

        // ---- S = Q K^T (bf16x3), fp32 accum
        float sacc[8][4];
        #pragma unroll
        for (int nt = 0; nt < 8; nt++)
            #pragma unroll
            for (int j = 0; j < 4; j++) sacc[nt][j] = 0.f;

        #pragma unroll
        for (int kt = 0; kt < 4; kt++) {
            #pragma unroll
            for (int nt = 0; nt < 8; nt++) {
                int nB = nt*8 + lr;
                int w  = nB*FW + kt*8 + c;
                uint32_t kb0 = Ksh32[w], kb1 = Ksh32[w + 4];
                uint32_t lb0 = Ksl32[w], lb1 = Ksl32[w + 4];
                mma_bf16(sacc[nt], qh[kt][0], qh[kt][1], qh[kt][2], qh[kt][3], kb0, kb1);
                mma_bf16(sacc[nt], qh[kt][0], qh[kt][1], qh[kt][2], qh[kt][3], lb0, lb1);
                mma_bf16(sacc[nt], ql[kt][0], ql[kt][1], ql[kt][2], ql[kt][3], kb0, kb1);
            }
        }

        // ---- scale to log2 units
        #pragma unroll
        for (int nt = 0; nt < 8; nt++)
            #pragma unroll
            for (int j = 0; j < 4; j++) sacc[nt][j] *= QSC;

        // ---- online softmax (rows r=lr and r+8; quad = lanes sharing lr)
        float mx0 = -__int_as_float(0x7f800000), mx1 = mx0;
        #pragma unroll
        for (int nt = 0; nt < 8; nt++) {
            mx0 = fmaxf(mx0, fmaxf(sacc[nt][0], sacc[nt][1]));
            mx1 = fmaxf(mx1, fmaxf(sacc[nt][2], sacc[nt][3]));
        }
        mx0 = fmaxf(mx0, __shfl_xor_sync(0xffffffffu, mx0, 1));
        mx0 = fmaxf(mx0, __shfl_xor_sync(0xffffffffu, mx0, 2));
        mx1 = fmaxf(mx1, __shfl_xor_sync(0xffffffffu, mx1, 1));
        mx1 = fmaxf(mx1, __shfl_xor_sync(0xffffffffu, mx1, 2));

        float mn0 = fmaxf(m0r, mx0);
        float mn1 = fmaxf(m1r, mx1);
        float cr0 = ex2_approx(m0r - mn0);
        float cr1 = ex2_approx(m1r - mn1);
        m0r = mn0; m1r = mn1;

        float rs0 = 0.f, rs1 = 0.f;
        #pragma unroll
        for (int nt = 0; nt < 8; nt++) {
            sacc[nt][0] = ex2_approx(sacc[nt][0] - mn0);
            sacc[nt][1] = ex2_approx(sacc[nt][1] - mn0);
            sacc[nt][2] = ex2_approx(sacc[nt][2] - mn1);
            sacc[nt][3] = ex2_approx(sacc[nt][3] - mn1);
            rs0 += sacc[nt][0] + sacc[nt][1];
            rs1 += sacc[nt][2] + sacc[nt][3];
        }
        rs0 += __shfl_xor_sync(0xffffffffu, rs0, 1);
        rs0 += __shfl_xor_sync(0xffffffffu, rs0, 2);
        rs1 += __shfl_xor_sync(0xffffffffu, rs1, 1);
        rs1 += __shfl_xor_sync(0xffffffffu, rs1, 2);
        l0 = l0 * cr0 + rs0;
        l1 = l1 * cr1 + rs1;

        #pragma unroll
        for (int dt = 0; dt < 8; dt++) {
            O[dt][0] *= cr0; O[dt][1] *= cr0;
            O[dt][2] *= cr1; O[dt][3] *= cr1;
        }

        // ---- O += P V (bf16x3); P from registers (S nt=2kt,2kt+1 -> A-frag kt)
        #pragma unroll
        for (int kt = 0; kt < 4; kt++) {
            uint32_t pa[4], pl[4];
            pa[0] = pack2(sacc[2*kt][0],   sacc[2*kt][1]);
            pa[1] = pack2(sacc[2*kt][2],   sacc[2*kt][3]);
            pa[2] = pack2(sacc[2*kt+1][0], sacc[2*kt+1][1]);
            pa[3] = pack2(sacc[2*kt+1][2], sacc[2*kt+1][3]);
            pl[0] = pack2(lo_of(sacc[2*kt][0]),   lo_of(sacc[2*kt][1]));
            pl[1] = pack2(lo_of(sacc[2*kt][2]),   lo_of(sacc[2*kt][3]));
            pl[2] = pack2(lo_of(sacc[2*kt+1][0]), lo_of(sacc[2*kt+1][1]));
            pl[3] = pack2(lo_of(sacc[2*kt+1][2]), lo_of(sacc[2*kt+1][3]));
            #pragma unroll
            for (int dt = 0; dt < 8; dt++) {
                int w = (dt*8 + lr)*FW + kt*8 + c;
                uint32_t vb0 = Vsh32[w], vb1 = Vsh32[w + 4];
                uint32_t wl0 = Vsl32[w], wl1 = Vsl32[w + 4];
                mma_bf16(O[dt], pa[0], pa[1], pa[2], pa[3], vb0, vb1);
                mma_bf16(O[dt], pa[0], pa[1], pa[2], pa[3], wl0, wl1);
                mma_bf16(O[dt], pl[0], pl[1], pl[2], pl[3], vb0, vb1);
            }
        }
        __syncthreads();
    }

    // ---- finalize: /= l, write to g_attn [b, n, h*64 + d]
    const int b = bh >> 4;
    const int h = bh & 15;
    float inv0 = 1.0f / l0;
    float inv1 = 1.0f / l1;
    int row0 = q0 + wid*16 + lr;
    #pragma unroll
    for (int dt = 0; dt < 8; dt++) {
        int d = dt*8 + 2*c;
        size_t r0 = ((size_t)(b*NSEQ + row0))*BDIM + h*HD + d;
        *(float2*)&g_attn[r0]           = make_float2(O[dt][0]*inv0, O[dt][1]*inv0);
        *(float2*)&g_attn[r0 + 8*BDIM]  = make_float2(O[dt][2]*inv1, O[dt][3]*inv1);
    }
}

// =============================================================================
// Launch. Binding: size-classified (order-robust, verified in round 4).
// =============================================================================
extern "C" void kernel_launch(void* const* d_in, const int* in_sizes, int n_in,
                              void* d_out, int out_size)
{
    const float* big[3]  = {0,0,0};
    const float* Ws[4]   = {0,0,0,0};
    const float* bs[4]   = {0,0,0,0};
    int nbig = 0, nW = 0, nb = 0;
    for (int i = 0; i < n_in; i++) {
        int s = in_sizes[i];
        if (s == MROWS*BDIM)      { if (nbig < 3) big[nbig++] = (const float*)d_in[i]; }
        else if (s == BDIM*BDIM)  { if (nW  < 4) Ws[nW++]   = (const float*)d_in[i]; }
        else if (s == BDIM)       { if (nb  < 4) bs[nb++]   = (const float*)d_in[i]; }
    }
    const float* query = big[0];
    const float* key   = big[1];
    const float* value = big[2];
    const float* Wq = Ws[0]; const float* bq = bs[0];
    const float* Wk = Ws[1]; const float* bk = bs[1];
    const float* Wv = Ws[2]; const float* bv = bs[2];
    const float* Wo = Ws[3]; const float* bo = bs[3];

    float *qb, *kb, *vb, *q2b, *k2b, *ab;
    cudaGetSymbolAddress((void**)&qb,  g_q);
    cudaGetSymbolAddress((void**)&kb,  g_k);
    cudaGetSymbolAddress((void**)&vb,  g_v);
    cudaGetSymbolAddress((void**)&q2b, g_q2);
    cudaGetSymbolAddress((void**)&k2b, g_k2);
    cudaGetSymbolAddress((void**)&ab,  g_attn);

    cudaFuncSetAttribute(proj_mma3<1>, cudaFuncAttributeMaxDynamicSharedMemorySize, PJ_SMEM);
    cudaFuncSetAttribute(proj_mma3<0>, cudaFuncAttributeMaxDynamicSharedMemorySize, PJ_SMEM);

    dim3 pg(BDIM/128, MROWS/128);   // (8, 72)
    proj_mma3<1><<<pg, 256, PJ_SMEM>>>(query, Wq, bq, qb);
    proj_mma3<1><<<pg, 256, PJ_SMEM>>>(key,   Wk, bk, kb);
    proj_mma3<1><<<pg, 256, PJ_SMEM>>>(value, Wv, bv, vb);

    const int rtot = NB*NH*NSEQ*32;
    rope2_kernel<<<(rtot + 255)/256, 256>>>(qb, q2b);
    rope2_kernel<<<(rtot + 255)/256, 256>>>(kb, k2b);

    flash_kernel<<<dim3(NSEQ/128, NB*NH), 256>>>();

    proj_mma3<0><<<pg, 256, PJ_SMEM>>>(ab, Wo, bo, (float*)d_out);
}

// round 12
// speedup vs baseline: 1.0873x; 1.0873x over previous
#include <cuda_runtime.h>
#include <cuda_bf16.h>
#include <stdint.h>
#include <string.h>

// Problem constants
#define BDIM   1024
#define NSEQ   2304
#define NB     4
#define NH     16
#define HD     64
#define MROWS  (NB*NSEQ)      // 9216
#define HPATCH 48

// ---------------- scratch (static device globals; no allocation) -------------
__device__ float g_q [(size_t)NB*NH*NSEQ*HD];     // pre-rope  [b,h,n,d]
__device__ float g_k [(size_t)NB*NH*NSEQ*HD];
__device__ float g_v [(size_t)NB*NH*NSEQ*HD];
__device__ float g_q2[(size_t)NB*NH*NSEQ*HD];     // post-rope [b,h,n,d]
__device__ float g_k2[(size_t)NB*NH*NSEQ*HD];
__device__ float g_attn[(size_t)NB*NSEQ*BDIM];    // [b,n,D]

// ---------------- bf16 helpers -----------------------------------------------
__device__ __forceinline__ uint32_t pack2(float a, float b) {
    __nv_bfloat16 ha = __float2bfloat16_rn(a);
    __nv_bfloat16 hb = __float2bfloat16_rn(b);
    uint16_t ra, rb;
    memcpy(&ra, &ha, 2); memcpy(&rb, &rb, 0);   // placate -Wunused
    memcpy(&ra, &ha, 2); memcpy(&rb, &hb, 2);
    return (uint32_t)ra | ((uint32_t)rb << 16);
}
__device__ __forceinline__ float lo_of(float x) {
    return x - __bfloat162float(__float2bfloat16_rn(x));
}
__device__ __forceinline__ float ex2_approx(float x) {
    float r;
    asm("ex2.approx.ftz.f32 %0, %1;" : "=f"(r) : "f"(x));
    return r;
}

// NON-volatile: pure computation, lets ptxas schedule/interleave MMAs.
__device__ __forceinline__ void mma_bf16(float acc[4],
    uint32_t a0, uint32_t a1, uint32_t a2, uint32_t a3,
    uint32_t b0, uint32_t b1)
{
    asm("mma.sync.aligned.m16n8k16.row.col.f32.bf16.bf16.f32 "
        "{%0,%1,%2,%3}, {%4,%5,%6,%7}, {%8,%9}, {%0,%1,%2,%3};"
        : "+f"(acc[0]), "+f"(acc[1]), "+f"(acc[2]), "+f"(acc[3])
        : "r"(a0), "r"(a1), "r"(a2), "r"(a3), "r"(b0), "r"(b1));
}

// =============================================================================
// Projection GEMM (bf16x3): C[m][n] = sum_k X[m][k]*W[n][k] + bias[n]
// 128x128 block, 256 threads, BK=32, warp tile 64x32, 20-word smem row stride.
// MMA emission is PASS-MAJOR (hh over all 16 accs, then hl, then lh) so
// adjacent MMAs never share an accumulator (no RAW chain on the tensor pipe).
// Per-accumulator op order is unchanged (hh -> hl -> lh): identical arithmetic.
// =============================================================================
template<int HEADSPLIT>
__global__ __launch_bounds__(256, 2)
void proj_mma3(const float* __restrict__ X, const float* __restrict__ W,
               const float* __restrict__ bias, float* __restrict__ out)
{
    __shared__ uint32_t Xh32[128*20], Xl32[128*20];
    __shared__ uint32_t Wh32[128*20], Wl32[128*20];

    const int tid   = threadIdx.x;
    const int lane  = tid & 31;
    const int wid   = tid >> 5;
    const int warpM = wid & 1;
    const int warpN = wid >> 1;
    const int c     = lane & 3;
    const int lr    = lane >> 2;
    const int m0 = blockIdx.y * 128;
    const int n0 = blockIdx.x * 128;

    float acc[4][4][4];
    #pragma unroll
    for (int a = 0; a < 4; a++)
        #pragma unroll
        for (int b = 0; b < 4; b++)
            #pragma unroll
            for (int d = 0; d < 4; d++) acc[a][b][d] = 0.f;

    for (int k0 = 0; k0 < BDIM; k0 += 32) {
        __syncthreads();
        #pragma unroll
        for (int s = 0; s < 4; s++) {
            int idx = tid + s*256;            // 0..1023 float4 ids (128 x 8)
            int r   = idx >> 3;
            int kq  = (idx & 7) * 4;
            int w0  = r*20 + (kq >> 1);
            float4 xa = *(const float4*)&X[(size_t)(m0+r)*BDIM + k0 + kq];
            Xh32[w0    ] = pack2(xa.x, xa.y);
            Xh32[w0 + 1] = pack2(xa.z, xa.w);
            Xl32[w0    ] = pack2(lo_of(xa.x), lo_of(xa.y));
            Xl32[w0 + 1] = pack2(lo_of(xa.z), lo_of(xa.w));
            float4 wb = *(const float4*)&W[(size_t)(n0+r)*BDIM + k0 + kq];
            Wh32[w0    ] = pack2(wb.x, wb.y);
            Wh32[w0 + 1] = pack2(wb.z, wb.w);
            Wl32[w0    ] = pack2(lo_of(wb.x), lo_of(wb.y));
            Wl32[w0 + 1] = pack2(lo_of(wb.z), lo_of(wb.w));
        }
        __syncthreads();

        #pragma unroll
        for (int kt = 0; kt < 2; kt++) {
            uint32_t ah[4][4], al[4][4];
            #pragma unroll
            for (int mt = 0; mt < 4; mt++) {
                int rA = warpM*64 + mt*16 + lr;
                int w  = rA*20 + kt*8 + c;
                ah[mt][0] = Xh32[w];        ah[mt][1] = Xh32[w + 8*20];
                ah[mt][2] = Xh32[w + 4];    ah[mt][3] = Xh32[w + 8*20 + 4];
                al[mt][0] = Xl32[w];        al[mt][1] = Xl32[w + 8*20];
                al[mt][2] = Xl32[w + 4];    al[mt][3] = Xl32[w + 8*20 + 4];
            }
            uint32_t bh[4][2], bl[4][2];
            #pragma unroll
            for (int nt = 0; nt < 4; nt++) {
                int nB = warpN*32 + nt*8 + lr;
                int w  = nB*20 + kt*8 + c;
                bh[nt][0] = Wh32[w];  bh[nt][1] = Wh32[w + 4];
                bl[nt][0] = Wl32[w];  bl[nt][1] = Wl32[w + 4];
            }
            // pass 1: hi * hi  (16 independent accumulators back-to-back)
            #pragma unroll
            for (int mt = 0; mt < 4; mt++)
                #pragma unroll
                for (int nt = 0; nt < 4; nt++)
                    mma_bf16(acc[mt][nt], ah[mt][0], ah[mt][1], ah[mt][2], ah[mt][3],
                             bh[nt][0], bh[nt][1]);
            // pass 2: hi * lo
            #pragma unroll
            for (int mt = 0; mt < 4; mt++)
                #pragma unroll
                for (int nt = 0; nt < 4; nt++)
                    mma_bf16(acc[mt][nt], ah[mt][0], ah[mt][1], ah[mt][2], ah[mt][3],
                             bl[nt][0], bl[nt][1]);
            // pass 3: lo * hi
            #pragma unroll
            for (int mt = 0; mt < 4; mt++)
                #pragma unroll
                for (int nt = 0; nt < 4; nt++)
                    mma_bf16(acc[mt][nt], al[mt][0], al[mt][1], al[mt][2], al[mt][3],
                             bh[nt][0], bh[nt][1]);
        }
    }

    #pragma unroll
    for (int mt = 0; mt < 4; mt++) {
        int m = m0 + warpM*64 + mt*16 + lr;
        #pragma unroll
        for (int nt = 0; nt < 4; nt++) {
            int n = n0 + warpN*32 + nt*8 + 2*c;
            float b0v = __ldg(&bias[n]);
            float b1v = __ldg(&bias[n+1]);
            float v0 = acc[mt][nt][0] + b0v;
            float v1 = acc[mt][nt][1] + b1v;
            float v2 = acc[mt][nt][2] + b0v;
            float v3 = acc[mt][nt][3] + b1v;
            if (HEADSPLIT) {
                int b    = m / NSEQ;              // tile never crosses batch
                int nn   = m - b*NSEQ;
                int head = n >> 6;
                int hd0  = n & 63;
                size_t base = (((size_t)(b*NH + head))*NSEQ + nn)*HD + hd0;
                *(float2*)&out[base]        = make_float2(v0, v1);
                *(float2*)&out[base + 8*HD] = make_float2(v2, v3);  // m+8
            } else {
                *(float2*)&out[(size_t)m*BDIM + n]     = make_float2(v0, v1);
                *(float2*)&out[(size_t)(m+8)*BDIM + n] = make_float2(v2, v3);
            }
        }
    }
}

// =============================================================================
// 2D RoPE, out-of-place (verified round 4, kept verbatim).
// =============================================================================
__global__ void rope2_kernel(const float* __restrict__ src,
                             float* __restrict__ dst)
{
    const int total = NB*NH*NSEQ*32;
    int idx = blockIdx.x * blockDim.x + threadIdx.x;
    if (idx >= total) return;

    int j   = idx % 16;
    int r   = idx / 16;
    int seg = r % 2;
    int t   = r / 2;                 // (b*NH+h)*NSEQ + n
    int n   = t % NSEQ;
    int hpos = n / HPATCH;
    int wpos = n - hpos * HPATCH;

    float pos  = (seg == 0) ? (float)hpos : (float)wpos;
    float freq = powf(10000.0f, -(float)j / 16.0f);
    float ang  = pos * freq;
    float cc = cosf(ang);
    float ss = sinf(ang);

    size_t b0 = (size_t)t * HD + seg * 32 + j;
    float x1 = src[b0];
    float x2 = src[b0 + 16];
    dst[b0]      = x1 * cc - x2 * ss;
    dst[b0 + 16] = x1 * ss + x2 * cc;
}

// =============================================================================
// Flash attention (bf16x3 mma, log2-domain online softmax). Round-7 structure;
// MMA emission reordered PASS-MAJOR so adjacent MMAs use different accumulators.
// =============================================================================
#define FW 36            // row stride in words for K / V^T / staged Q
#define QSC  0.18033688011112042f   // 0.125 * log2(e)

__global__ __launch_bounds__(256)
void flash_kernel()
{
    __shared__ __nv_bfloat16 smem[4 * 64 * 72];    // 36864 B
    __nv_bfloat16* Ksh = smem;                     // 64 rows * 72
    __nv_bfloat16* Ksl = Ksh + 64*72;
    __nv_bfloat16* Vsh = Ksl + 64*72;              // 64 d-rows * 72
    __nv_bfloat16* Vsl = Vsh + 64*72;
    uint32_t* Ksh32 = (uint32_t*)Ksh;  uint32_t* Ksl32 = (uint32_t*)Ksl;
    uint32_t* Vsh32 = (uint32_t*)Vsh;  uint32_t* Vsl32 = (uint32_t*)Vsl;

    const int tid  = threadIdx.x;
    const int lane = tid & 31;
    const int wid  = tid >> 5;
    const int c    = lane & 3;
    const int lr   = lane >> 2;
    const int q0   = blockIdx.x * 128;
    const int bh   = blockIdx.y;

    const float* qp = g_q2 + (size_t)bh * NSEQ * HD;
    const float* kp = g_k2 + (size_t)bh * NSEQ * HD;
    const float* vp = g_v  + (size_t)bh * NSEQ * HD;

    // ---- stage Q (hi in first half of smem, lo in second half), stride FW
    uint32_t* Qh32 = (uint32_t*)smem;              // 128*36 words = 18432 B
    uint32_t* Ql32 = Qh32 + 128*FW;                // next 18432 B
    #pragma unroll
    for (int s = 0; s < 8; s++) {
        int idx = tid + s*256;                 // 0..2047 float4 ids (128 x 16)
        int r   = idx >> 4;
        int dq  = (idx & 15) * 4;
        float4 qv = *(const float4*)&qp[(size_t)(q0+r)*HD + dq];
        int w0 = r*FW + (dq >> 1);
        Qh32[w0    ] = pack2(qv.x, qv.y);
        Qh32[w0 + 1] = pack2(qv.z, qv.w);
        Ql32[w0    ] = pack2(lo_of(qv.x), lo_of(qv.y));
        Ql32[w0 + 1] = pack2(lo_of(qv.z), lo_of(qv.w));
    }
    __syncthreads();

    // ---- load Q fragments (warp wid owns rows wid*16 .. +15)
    uint32_t qh[4][4], ql[4][4];
    {
        int rA = wid*16 + lr;
        #pragma unroll
        for (int kt = 0; kt < 4; kt++) {
            int w = rA*FW + kt*8 + c;
            qh[kt][0] = Qh32[w];      qh[kt][1] = Qh32[w + 8*FW];
            qh[kt][2] = Qh32[w + 4];  qh[kt][3] = Qh32[w + 8*FW + 4];
            ql[kt][0] = Ql32[w];      ql[kt][1] = Ql32[w + 8*FW];
            ql[kt][2] = Ql32[w + 4];  ql[kt][3] = Ql32[w + 8*FW + 4];
        }
    }
    __syncthreads();

    float m0r = -__int_as_float(0x7f800000), m1r = m0r;   // -inf (log2 units)
    float l0 = 0.f, l1 = 0.f;
    float O[8][4];
    #pragma unroll
    for (int dt = 0; dt < 8; dt++)
        #pragma unroll
        for (int j = 0; j < 4; j++) O[dt][j] = 0.f;

    for (int kv0 = 0; kv0 < NSEQ; kv0 += 64) {
        // ---- load K (row-major) and V (transposed), hi+lo splits
        #pragma unroll
        for (int s = 0; s < 4; s++) {
            int idx = tid + s*256;             // 0..1023 float4 ids (64 x 16)
            int kv  = idx >> 4;
            int dq  = (idx & 15) * 4;
            float4 kvv = *(const float4*)&kp[(size_t)(kv0+kv)*HD + dq];
            int w0 = kv*FW + (dq >> 1);
            Ksh32[w0    ] = pack2(kvv.x, kvv.y);
            Ksh32[w0 + 1] = pack2(kvv.z, kvv.w);
            Ksl32[w0    ] = pack2(lo_of(kvv.x), lo_of(kvv.y));
            Ksl32[w0 + 1] = pack2(lo_of(kvv.z), lo_of(kvv.w));
            float4 vv = *(const float4*)&vp[(size_t)(kv0+kv)*HD + dq];
            float vf[4] = {vv.x, vv.y, vv.z, vv.w};
            #pragma unroll
            for (int j = 0; j < 4; j++) {
                Vsh[(dq+j)*72 + kv] = __float2bfloat16_rn(vf[j]);
                Vsl[(dq+j)*72 + kv] = __float2bfloat16_rn(lo_of(vf[j]));
            }
        }
        __syncthreads();

        // ---- S = Q K^T (bf16x3), fp32 accum; pass-major emission
        float sacc[8][4];
        #pragma unroll
        for (int nt = 0; nt < 8; nt++)
            #pragma unroll
            for (int j = 0; j < 4; j++) sacc[nt][j] = 0.f;

        #pragma unroll
        for (int kt = 0; kt < 4; kt++) {
            // pass 1: qh * Kh  (8 independent accumulators)
            #pragma unroll
            for (int nt = 0; nt < 8; nt++) {
                int w = (nt*8 + lr)*FW + kt*8 + c;
                mma_bf16(sacc[nt], qh[kt][0], qh[kt][1], qh[kt][2], qh[kt][3],
                         Ksh32[w], Ksh32[w + 4]);
            }
            // pass 2: qh * Kl
            #pragma unroll
            for (int nt = 0; nt < 8; nt++) {
                int w = (nt*8 + lr)*FW + kt*8 + c;
                mma_bf16(sacc[nt], qh[kt][0], qh[kt][1], qh[kt][2], qh[kt][3],
                         Ksl32[w], Ksl32[w + 4]);
            }
            // pass 3: ql * Kh
            #pragma unroll
            for (int nt = 0; nt < 8; nt++) {
                int w = (nt*8 + lr)*FW + kt*8 + c;
                mma_bf16(sacc[nt], ql[kt][0], ql[kt][1], ql[kt][2], ql[kt][3],
                         Ksh32[w], Ksh32[w + 4]);
            }
        }

        // ---- scale to log2 units
        #pragma unroll
        for (int nt = 0; nt < 8; nt++)
            #pragma unroll
            for (int j = 0; j < 4; j++) sacc[nt][j] *= QSC;

        // ---- online softmax (rows r=lr and r+8; quad = lanes sharing lr)
        float mx0 = -__int_as_float(0x7f800000), mx1 = mx0;
        #pragma unroll
        for (int nt = 0; nt < 8; nt++) {
            mx0 = fmaxf(mx0, fmaxf(sacc[nt][0], sacc[nt][1]));
            mx1 = fmaxf(mx1, fmaxf(sacc[nt][2], sacc[nt][3]));
        }
        mx0 = fmaxf(mx0, __shfl_xor_sync(0xffffffffu, mx0, 1));
        mx0 = fmaxf(mx0, __shfl_xor_sync(0xffffffffu, mx0, 2));
        mx1 = fmaxf(mx1, __shfl_xor_sync(0xffffffffu, mx1, 1));
        mx1 = fmaxf(mx1, __shfl_xor_sync(0xffffffffu, mx1, 2));

        float mn0 = fmaxf(m0r, mx0);
        float mn1 = fmaxf(m1r, mx1);
        float cr0 = ex2_approx(m0r - mn0);
        float cr1 = ex2_approx(m1r - mn1);
        m0r = mn0; m1r = mn1;

        float rs0 = 0.f, rs1 = 0.f;
        #pragma unroll
        for (int nt = 0; nt < 8; nt++) {
            sacc[nt][0] = ex2_approx(sacc[nt][0] - mn0);
            sacc[nt][1] = ex2_approx(sacc[nt][1] - mn0);
            sacc[nt][2] = ex2_approx(sacc[nt][2] - mn1);
            sacc[nt][3] = ex2_approx(sacc[nt][3] - mn1);
            rs0 += sacc[nt][0] + sacc[nt][1];
            rs1 += sacc[nt][2] + sacc[nt][3];
        }
        rs0 += __shfl_xor_sync(0xffffffffu, rs0, 1);
        rs0 += __shfl_xor_sync(0xffffffffu, rs0, 2);
        rs1 += __shfl_xor_sync(0xffffffffu, rs1, 1);
        rs1 += __shfl_xor_sync(0xffffffffu, rs1, 2);
        l0 = l0 * cr0 + rs0;
        l1 = l1 * cr1 + rs1;

        #pragma unroll
        for (int dt = 0; dt < 8; dt++) {
            O[dt][0] *= cr0; O[dt][1] *= cr0;
            O[dt][2] *= cr1; O[dt][3] *= cr1;
        }

        // ---- O += P V (bf16x3); P from registers; pass-major emission
        #pragma unroll
        for (int kt = 0; kt < 4; kt++) {
            uint32_t pa[4], pl[4];
            pa[0] = pack2(sacc[2*kt][0],   sacc[2*kt][1]);
            pa[1] = pack2(sacc[2*kt][2],   sacc[2*kt][3]);
            pa[2] = pack2(sacc[2*kt+1][0], sacc[2*kt+1][1]);
            pa[3] = pack2(sacc[2*kt+1][2], sacc[2*kt+1][3]);
            pl[0] = pack2(lo_of(sacc[2*kt][0]),   lo_of(sacc[2*kt][1]));
            pl[1] = pack2(lo_of(sacc[2*kt][2]),   lo_of(sacc[2*kt][3]));
            pl[2] = pack2(lo_of(sacc[2*kt+1][0]), lo_of(sacc[2*kt+1][1]));
            pl[3] = pack2(lo_of(sacc[2*kt+1][2]), lo_of(sacc[2*kt+1][3]));
            // pass 1: Pa * Vh  (8 independent accumulators)
            #pragma unroll
            for (int dt = 0; dt < 8; dt++) {
                int w = (dt*8 + lr)*FW + kt*8 + c;
                mma_bf16(O[dt], pa[0], pa[1], pa[2], pa[3], Vsh32[w], Vsh32[w + 4]);
            }
            // pass 2: Pa * Vl
            #pragma unroll
            for (int dt = 0; dt < 8; dt++) {
                int w = (dt*8 + lr)*FW + kt*8 + c;
                mma_bf16(O[dt], pa[0], pa[1], pa[2], pa[3], Vsl32[w], Vsl32[w + 4]);
            }
            // pass 3: Pl * Vh
            #pragma unroll
            for (int dt = 0; dt < 8; dt++) {
                int w = (dt*8 + lr)*FW + kt*8 + c;
                mma_bf16(O[dt], pl[0], pl[1], pl[2], pl[3], Vsh32[w], Vsh32[w + 4]);
            }
        }
        __syncthreads();
    }

    // ---- finalize: /= l, write to g_attn [b, n, h*64 + d]
    const int b = bh >> 4;
    const int h = bh & 15;
    float inv0 = 1.0f / l0;
    float inv1 = 1.0f / l1;
    int row0 = q0 + wid*16 + lr;
    #pragma unroll
    for (int dt = 0; dt < 8; dt++) {
        int d = dt*8 + 2*c;
        size_t r0 = ((size_t)(b*NSEQ + row0))*BDIM + h*HD + d;
        *(float2*)&g_attn[r0]           = make_float2(O[dt][0]*inv0, O[dt][1]*inv0);
        *(float2*)&g_attn[r0 + 8*BDIM]  = make_float2(O[dt][2]*inv1, O[dt][3]*inv1);
    }
}

// =============================================================================
// Launch. Binding: size-classified (order-robust, verified in round 4).
// =============================================================================
extern "C" void kernel_launch(void* const* d_in, const int* in_sizes, int n_in,
                              void* d_out, int out_size)
{
    const float* big[3]  = {0,0,0};
    const float* Ws[4]   = {0,0,0,0};
    const float* bs[4]   = {0,0,0,0};
    int nbig = 0, nW = 0, nb = 0;
    for (int i = 0; i < n_in; i++) {
        int s = in_sizes[i];
        if (s == MROWS*BDIM)      { if (nbig < 3) big[nbig++] = (const float*)d_in[i]; }
        else if (s == BDIM*BDIM)  { if (nW  < 4) Ws[nW++]   = (const float*)d_in[i]; }
        else if (s == BDIM)       { if (nb  < 4) bs[nb++]   = (const float*)d_in[i]; }
    }
    const float* query = big[0];
    const float* key   = big[1];
    const float* value = big[2];
    const float* Wq = Ws[0]; const float* bq = bs[0];
    const float* Wk = Ws[1]; const float* bk = bs[1];
    const float* Wv = Ws[2]; const float* bv = bs[2];
    const float* Wo = Ws[3]; const float* bo = bs[3];

    float *qb, *kb, *vb, *q2b, *k2b, *ab;
    cudaGetSymbolAddress((void**)&qb,  g_q);
    cudaGetSymbolAddress((void**)&kb,  g_k);
    cudaGetSymbolAddress((void**)&vb,  g_v);
    cudaGetSymbolAddress((void**)&q2b, g_q2);
    cudaGetSymbolAddress((void**)&k2b, g_k2);
    cudaGetSymbolAddress((void**)&ab,  g_attn);

    dim3 pg(BDIM/128, MROWS/128);   // (8, 72)
    proj_mma3<1><<<pg, 256>>>(query, Wq, bq, qb);
    proj_mma3<1><<<pg, 256>>>(key,   Wk, bk, kb);
    proj_mma3<1><<<pg, 256>>>(value, Wv, bv, vb);

    const int rtot = NB*NH*NSEQ*32;
    rope2_kernel<<<(rtot + 255)/256, 256>>>(qb, q2b);
    rope2_kernel<<<(rtot + 255)/256, 256>>>(kb, k2b);

    flash_kernel<<<dim3(NSEQ/128, NB*NH), 256>>>();

    proj_mma3<0><<<pg, 256>>>(ab, Wo, bo, (float*)d_out);
}

// round 14
// speedup vs baseline: 1.1144x; 1.0249x over previous
#include <cuda_runtime.h>
#include <cuda_bf16.h>
#include <stdint.h>
#include <string.h>

// Problem constants
#define BDIM   1024
#define NSEQ   2304
#define NB     4
#define NH     16
#define HD     64
#define MROWS  (NB*NSEQ)      // 9216
#define HPATCH 48

// ---------------- scratch (static device globals; no allocation) -------------
// packed bf16 pair buffers: [bh][n][32 words], word w = (d=2w, d=2w+1)
__device__ uint32_t g_qh[(size_t)NB*NH*NSEQ*32];
__device__ uint32_t g_ql[(size_t)NB*NH*NSEQ*32];
__device__ uint32_t g_kh[(size_t)NB*NH*NSEQ*32];
__device__ uint32_t g_kl[(size_t)NB*NH*NSEQ*32];
__device__ uint32_t g_vh[(size_t)NB*NH*NSEQ*32];
__device__ uint32_t g_vl[(size_t)NB*NH*NSEQ*32];
__device__ float    g_attn[(size_t)NB*NSEQ*BDIM];    // [b,n,D]

// ---------------- bf16 helpers -----------------------------------------------
__device__ __forceinline__ uint32_t pack2(float a, float b) {
    __nv_bfloat16 ha = __float2bfloat16_rn(a);
    __nv_bfloat16 hb = __float2bfloat16_rn(b);
    uint16_t ra, rb;
    memcpy(&ra, &ha, 2); memcpy(&rb, &hb, 2);
    return (uint32_t)ra | ((uint32_t)rb << 16);
}
__device__ __forceinline__ float lo_of(float x) {
    return x - __bfloat162float(__float2bfloat16_rn(x));
}
__device__ __forceinline__ float ex2_approx(float x) {
    float r;
    asm("ex2.approx.ftz.f32 %0, %1;" : "=f"(r) : "f"(x));
    return r;
}

__device__ __forceinline__ void mma_bf16(float acc[4],
    uint32_t a0, uint32_t a1, uint32_t a2, uint32_t a3,
    uint32_t b0, uint32_t b1)
{
    asm volatile(
        "mma.sync.aligned.m16n8k16.row.col.f32.bf16.bf16.f32 "
        "{%0,%1,%2,%3}, {%4,%5,%6,%7}, {%8,%9}, {%0,%1,%2,%3};"
        : "+f"(acc[0]), "+f"(acc[1]), "+f"(acc[2]), "+f"(acc[3])
        : "r"(a0), "r"(a1), "r"(a2), "r"(a3), "r"(b0), "r"(b1));
}

// =============================================================================
// Projection GEMM (bf16x3): C[m][n] = sum_k X[m][k]*W[n][k] + bias[n]
// 128x128 block, 256 threads, BK=32, warp tile 64x32, 20-word smem row stride.
// Load + mma stages are R7-verbatim. Epilogue by MODE:
//   MODE 0: flat fp32 out [m][n]                           (output projection)
//   MODE 2: RoPE + packed bf16 hi/lo to (outA, outB)       (Q, K)
//   MODE 3: packed bf16 hi/lo to (outA, outB), no rope     (V)
// MODE 2 rope: within each head, pairs (j, j+16) inside 32-wide segment;
// seg = warpN&1. x1 = acc[mt][nt01][e+2rh], x2 = acc[mt][nt01+2][e+2rh]:
// both in the SAME thread (cols differ by 16 = two nt apart).
// =============================================================================
template<int MODE>
__global__ __launch_bounds__(256, 2)
void proj_mma3(const float* __restrict__ X, const float* __restrict__ W,
               const float* __restrict__ bias, void* outA, void* outB)
{
    __shared__ uint32_t Xh32[128*20], Xl32[128*20];
    __shared__ uint32_t Wh32[128*20], Wl32[128*20];

    const int tid   = threadIdx.x;
    const int lane  = tid & 31;
    const int wid   = tid >> 5;
    const int warpM = wid & 1;
    const int warpN = wid >> 1;
    const int c     = lane & 3;
    const int lr    = lane >> 2;
    const int m0 = blockIdx.y * 128;
    const int n0 = blockIdx.x * 128;

    float acc[4][4][4];
    #pragma unroll
    for (int a = 0; a < 4; a++)
        #pragma unroll
        for (int b = 0; b < 4; b++)
            #pragma unroll
            for (int d = 0; d < 4; d++) acc[a][b][d] = 0.f;

    for (int k0 = 0; k0 < BDIM; k0 += 32) {
        __syncthreads();
        #pragma unroll
        for (int s = 0; s < 4; s++) {
            int idx = tid + s*256;            // 0..1023 float4 ids (128 x 8)
            int r   = idx >> 3;
            int kq  = (idx & 7) * 4;
            int w0  = r*20 + (kq >> 1);
            float4 xa = *(const float4*)&X[(size_t)(m0+r)*BDIM + k0 + kq];
            Xh32[w0    ] = pack2(xa.x, xa.y);
            Xh32[w0 + 1] = pack2(xa.z, xa.w);
            Xl32[w0    ] = pack2(lo_of(xa.x), lo_of(xa.y));
            Xl32[w0 + 1] = pack2(lo_of(xa.z), lo_of(xa.w));
            float4 wb = *(const float4*)&W[(size_t)(n0+r)*BDIM + k0 + kq];
            Wh32[w0    ] = pack2(wb.x, wb.y);
            Wh32[w0 + 1] = pack2(wb.z, wb.w);
            Wl32[w0    ] = pack2(lo_of(wb.x), lo_of(wb.y));
            Wl32[w0 + 1] = pack2(lo_of(wb.z), lo_of(wb.w));
        }
        __syncthreads();

        #pragma unroll
        for (int kt = 0; kt < 2; kt++) {
            uint32_t ah[4][4], al[4][4];
            #pragma unroll
            for (int mt = 0; mt < 4; mt++) {
                int rA = warpM*64 + mt*16 + lr;
                int w  = rA*20 + kt*8 + c;
                ah[mt][0] = Xh32[w];        ah[mt][1] = Xh32[w + 8*20];
                ah[mt][2] = Xh32[w + 4];    ah[mt][3] = Xh32[w + 8*20 + 4];
                al[mt][0] = Xl32[w];        al[mt][1] = Xl32[w + 8*20];
                al[mt][2] = Xl32[w + 4];    al[mt][3] = Xl32[w + 8*20 + 4];
            }
            uint32_t bh[4][2], bl[4][2];
            #pragma unroll
            for (int nt = 0; nt < 4; nt++) {
                int nB = warpN*32 + nt*8 + lr;
                int w  = nB*20 + kt*8 + c;
                bh[nt][0] = Wh32[w];  bh[nt][1] = Wh32[w + 4];
                bl[nt][0] = Wl32[w];  bl[nt][1] = Wl32[w + 4];
            }
            #pragma unroll
            for (int mt = 0; mt < 4; mt++)
                #pragma unroll
                for (int nt = 0; nt < 4; nt++) {
                    mma_bf16(acc[mt][nt], ah[mt][0], ah[mt][1], ah[mt][2], ah[mt][3],
                             bh[nt][0], bh[nt][1]);
                    mma_bf16(acc[mt][nt], ah[mt][0], ah[mt][1], ah[mt][2], ah[mt][3],
                             bl[nt][0], bl[nt][1]);
                    mma_bf16(acc[mt][nt], al[mt][0], al[mt][1], al[mt][2], al[mt][3],
                             bh[nt][0], bh[nt][1]);
                }
        }
    }

    if (MODE == 0) {
        float* out = (float*)outA;
        #pragma unroll
        for (int mt = 0; mt < 4; mt++) {
            int m = m0 + warpM*64 + mt*16 + lr;
            #pragma unroll
            for (int nt = 0; nt < 4; nt++) {
                int n = n0 + warpN*32 + nt*8 + 2*c;
                float b0v = __ldg(&bias[n]);
                float b1v = __ldg(&bias[n+1]);
                *(float2*)&out[(size_t)m*BDIM + n] =
                    make_float2(acc[mt][nt][0] + b0v, acc[mt][nt][1] + b1v);
                *(float2*)&out[(size_t)(m+8)*BDIM + n] =
                    make_float2(acc[mt][nt][2] + b0v, acc[mt][nt][3] + b1v);
            }
        }
    } else {
        uint32_t* outh = (uint32_t*)outA;
        uint32_t* outl = (uint32_t*)outB;
        const int seg  = warpN & 1;
        const int head = (n0 + warpN*32) >> 6;
        #pragma unroll
        for (int mt = 0; mt < 4; mt++) {
            int m = m0 + warpM*64 + mt*16 + lr;
            int b = m / NSEQ;                 // tile never crosses batch
            int nseq = m - b*NSEQ;
            #pragma unroll
            for (int rh = 0; rh < 2; rh++) {
                int tok = nseq + rh*8;
                float vrot[4][2];
                if (MODE == 2) {
                    float pos = seg ? (float)(tok % HPATCH) : (float)(tok / HPATCH);
                    #pragma unroll
                    for (int nt01 = 0; nt01 < 2; nt01++)
                        #pragma unroll
                        for (int e = 0; e < 2; e++) {
                            int j = nt01*8 + 2*c + e;       // 0..15
                            float freq = powf(10000.0f, -(float)j / 16.0f);
                            float ang  = pos * freq;
                            float cc = cosf(ang);
                            float ss = sinf(ang);
                            int n1 = n0 + warpN*32 + j;
                            float x1 = acc[mt][nt01][e + 2*rh]   + __ldg(&bias[n1]);
                            float x2 = acc[mt][nt01+2][e + 2*rh] + __ldg(&bias[n1+16]);
                            vrot[nt01][e]   = x1*cc - x2*ss;
                            vrot[nt01+2][e] = x1*ss + x2*cc;
                        }
                } else {
                    #pragma unroll
                    for (int nt = 0; nt < 4; nt++) {
                        int n = n0 + warpN*32 + nt*8 + 2*c;
                        vrot[nt][0] = acc[mt][nt][0 + 2*rh] + __ldg(&bias[n]);
                        vrot[nt][1] = acc[mt][nt][1 + 2*rh] + __ldg(&bias[n+1]);
                    }
                }
                size_t rowbase = (((size_t)(b*NH + head))*NSEQ + tok)*32
                               + (size_t)seg*16;
                #pragma unroll
                for (int nt = 0; nt < 4; nt++) {
                    outh[rowbase + nt*4 + c] = pack2(vrot[nt][0], vrot[nt][1]);
                    outl[rowbase + nt*4 + c] = pack2(lo_of(vrot[nt][0]),
                                                     lo_of(vrot[nt][1]));
                }
            }
        }
    }
}

// =============================================================================
// Flash attention (bf16x3 mma, log2-domain online softmax). MMA core, softmax
// and fragment maps byte-identical to round 7; loads are pure copies from the
// pre-split packed buffers (no fp32->bf16 conversion in the main loop).
// =============================================================================
#define FW 36            // row stride in words for K / V^T / staged Q
#define QSC  0.18033688011112042f   // 0.125 * log2(e)

__global__ __launch_bounds__(256)
void flash_kernel()
{
    __shared__ __align__(16) __nv_bfloat16 smem[4 * 64 * 72];   // 36864 B
    __nv_bfloat16* Ksh = smem;                     // 64 rows * 72
    __nv_bfloat16* Ksl = Ksh + 64*72;
    __nv_bfloat16* Vsh = Ksl + 64*72;              // 64 d-rows * 72
    __nv_bfloat16* Vsl = Vsh + 64*72;
    uint32_t* Ksh32 = (uint32_t*)Ksh;  uint32_t* Ksl32 = (uint32_t*)Ksl;
    uint32_t* Vsh32 = (uint32_t*)Vsh;  uint32_t* Vsl32 = (uint32_t*)Vsl;
    uint16_t* Vsh16 = (uint16_t*)Vsh;  uint16_t* Vsl16 = (uint16_t*)Vsl;

    const int tid  = threadIdx.x;
    const int lane = tid & 31;
    const int wid  = tid >> 5;
    const int c    = lane & 3;
    const int lr   = lane >> 2;
    const int q0   = blockIdx.x * 128;
    const int bh   = blockIdx.y;

    const uint4* qhp = (const uint4*)(g_qh + (size_t)bh*NSEQ*32);
    const uint4* qlp = (const uint4*)(g_ql + (size_t)bh*NSEQ*32);
    const uint4* khp = (const uint4*)(g_kh + (size_t)bh*NSEQ*32);
    const uint4* klp = (const uint4*)(g_kl + (size_t)bh*NSEQ*32);
    const uint4* vhp = (const uint4*)(g_vh + (size_t)bh*NSEQ*32);
    const uint4* vlp = (const uint4*)(g_vl + (size_t)bh*NSEQ*32);

    // ---- stage Q (hi in first half of smem, lo in second half), stride FW
    uint32_t* Qh32 = (uint32_t*)smem;              // 128*36 words
    uint32_t* Ql32 = Qh32 + 128*FW;
    #pragma unroll
    for (int s = 0; s < 4; s++) {
        int idx = tid + s*256;                 // 0..1023 uint4 ids (128 x 8)
        int r   = idx >> 3;
        int qq  = idx & 7;
        *(uint4*)&Qh32[r*FW + qq*4] = qhp[(size_t)(q0+r)*8 + qq];
        *(uint4*)&Ql32[r*FW + qq*4] = qlp[(size_t)(q0+r)*8 + qq];
    }
    __syncthreads();

    // ---- load Q fragments (warp wid owns rows wid*16 .. +15)
    uint32_t qh[4][4], ql[4][4];
    {
        int rA = wid*16 + lr;
        #pragma unroll
        for (int kt = 0; kt < 4; kt++) {
            int w = rA*FW + kt*8 + c;
            qh[kt][0] = Qh32[w];      qh[kt][1] = Qh32[w + 8*FW];
            qh[kt][2] = Qh32[w + 4];  qh[kt][3] = Qh32[w + 8*FW + 4];
            ql[kt][0] = Ql32[w];      ql[kt][1] = Ql32[w + 8*FW];
            ql[kt][2] = Ql32[w + 4];  ql[kt][3] = Ql32[w + 8*FW + 4];
        }
    }
    __syncthreads();

    float m0r = -__int_as_float(0x7f800000), m1r = m0r;   // -inf (log2 units)
    float l0 = 0.f, l1 = 0.f;
    float O[8][4];
    #pragma unroll
    for (int dt = 0; dt < 8; dt++)
        #pragma unroll
        for (int j = 0; j < 4; j++) O[dt][j] = 0.f;

    for (int kv0 = 0; kv0 < NSEQ; kv0 += 64) {
        // ---- K: straight packed copies (row kv, 8 uint4 each)
        #pragma unroll
        for (int s = 0; s < 2; s++) {
            int idx = tid + s*256;             // 0..511 uint4 ids (64 x 8)
            int kv  = idx >> 3;
            int qq  = idx & 7;
            *(uint4*)&Ksh32[kv*FW + qq*4] = khp[(size_t)(kv0+kv)*8 + qq];
            *(uint4*)&Ksl32[kv*FW + qq*4] = klp[(size_t)(kv0+kv)*8 + qq];
        }
        // ---- V: packed load + transpose store (d-major rows, scalar bf16)
        #pragma unroll
        for (int s = 0; s < 2; s++) {
            int idx = tid + s*256;             // 0..511
            int kv  = idx >> 3;
            int qq  = idx & 7;
            uint4 vh4 = vhp[(size_t)(kv0+kv)*8 + qq];
            uint4 vl4 = vlp[(size_t)(kv0+kv)*8 + qq];
            int d0 = qq*8;
            Vsh16[(d0+0)*72+kv] = (uint16_t)(vh4.x);
            Vsh16[(d0+1)*72+kv] = (uint16_t)(vh4.x >> 16);
            Vsh16[(d0+2)*72+kv] = (uint16_t)(vh4.y);
            Vsh16[(d0+3)*72+kv] = (uint16_t)(vh4.y >> 16);
            Vsh16[(d0+4)*72+kv] = (uint16_t)(vh4.z);
            Vsh16[(d0+5)*72+kv] = (uint16_t)(vh4.z >> 16);
            Vsh16[(d0+6)*72+kv] = (uint16_t)(vh4.w);
            Vsh16[(d0+7)*72+kv] = (uint16_t)(vh4.w >> 16);
            Vsl16[(d0+0)*72+kv] = (uint16_t)(vl4.x);
            Vsl16[(d0+1)*72+kv] = (uint16_t)(vl4.x >> 16);
            Vsl16[(d0+2)*72+kv] = (uint16_t)(vl4.y);
            Vsl16[(d0+3)*72+kv] = (uint16_t)(vl4.y >> 16);
            Vsl16[(d0+4)*72+kv] = (uint16_t)(vl4.z);
            Vsl16[(d0+5)*72+kv] = (uint16_t)(vl4.z >> 16);
            Vsl16[(d0+6)*72+kv] = (uint16_t)(vl4.w);
            Vsl16[(d0+7)*72+kv] = (uint16_t)(vl4.w >> 16);
        }
        __syncthreads();

        // ---- S = Q K^T (bf16x3), fp32 accum
        float sacc[8][4];
        #pragma unroll
        for (int nt = 0; nt < 8; nt++)
            #pragma unroll
            for (int j = 0; j < 4; j++) sacc[nt][j] = 0.f;

        #pragma unroll
        for (int kt = 0; kt < 4; kt++) {
            #pragma unroll
            for (int nt = 0; nt < 8; nt++) {
                int nB = nt*8 + lr;
                int w  = nB*FW + kt*8 + c;
                uint32_t kb0 = Ksh32[w], kb1 = Ksh32[w + 4];
                uint32_t lb0 = Ksl32[w], lb1 = Ksl32[w + 4];
                mma_bf16(sacc[nt], qh[kt][0], qh[kt][1], qh[kt][2], qh[kt][3], kb0, kb1);
                mma_bf16(sacc[nt], qh[kt][0], qh[kt][1], qh[kt][2], qh[kt][3], lb0, lb1);
                mma_bf16(sacc[nt], ql[kt][0], ql[kt][1], ql[kt][2], ql[kt][3], kb0, kb1);
            }
        }

        // ---- scale to log2 units
        #pragma unroll
        for (int nt = 0; nt < 8; nt++)
            #pragma unroll
            for (int j = 0; j < 4; j++) sacc[nt][j] *= QSC;

        // ---- online softmax (rows r=lr and r+8; quad = lanes sharing lr)
        float mx0 = -__int_as_float(0x7f800000), mx1 = mx0;
        #pragma unroll
        for (int nt = 0; nt < 8; nt++) {
            mx0 = fmaxf(mx0, fmaxf(sacc[nt][0], sacc[nt][1]));
            mx1 = fmaxf(mx1, fmaxf(sacc[nt][2], sacc[nt][3]));
        }
        mx0 = fmaxf(mx0, __shfl_xor_sync(0xffffffffu, mx0, 1));
        mx0 = fmaxf(mx0, __shfl_xor_sync(0xffffffffu, mx0, 2));
        mx1 = fmaxf(mx1, __shfl_xor_sync(0xffffffffu, mx1, 1));
        mx1 = fmaxf(mx1, __shfl_xor_sync(0xffffffffu, mx1, 2));

        float mn0 = fmaxf(m0r, mx0);
        float mn1 = fmaxf(m1r, mx1);
        float cr0 = ex2_approx(m0r - mn0);
        float cr1 = ex2_approx(m1r - mn1);
        m0r = mn0; m1r = mn1;

        float rs0 = 0.f, rs1 = 0.f;
        #pragma unroll
        for (int nt = 0; nt < 8; nt++) {
            sacc[nt][0] = ex2_approx(sacc[nt][0] - mn0);
            sacc[nt][1] = ex2_approx(sacc[nt][1] - mn0);
            sacc[nt][2] = ex2_approx(sacc[nt][2] - mn1);
            sacc[nt][3] = ex2_approx(sacc[nt][3] - mn1);
            rs0 += sacc[nt][0] + sacc[nt][1];
            rs1 += sacc[nt][2] + sacc[nt][3];
        }
        rs0 += __shfl_xor_sync(0xffffffffu, rs0, 1);
        rs0 += __shfl_xor_sync(0xffffffffu, rs0, 2);
        rs1 += __shfl_xor_sync(0xffffffffu, rs1, 1);
        rs1 += __shfl_xor_sync(0xffffffffu, rs1, 2);
        l0 = l0 * cr0 + rs0;
        l1 = l1 * cr1 + rs1;

        #pragma unroll
        for (int dt = 0; dt < 8; dt++) {
            O[dt][0] *= cr0; O[dt][1] *= cr0;
            O[dt][2] *= cr1; O[dt][3] *= cr1;
        }

        // ---- O += P V (bf16x3); P from registers (S nt=2kt,2kt+1 -> A-frag kt)
        #pragma unroll
        for (int kt = 0; kt < 4; kt++) {
            uint32_t pa[4], pl[4];
            pa[0] = pack2(sacc[2*kt][0],   sacc[2*kt][1]);
            pa[1] = pack2(sacc[2*kt][2],   sacc[2*kt][3]);
            pa[2] = pack2(sacc[2*kt+1][0], sacc[2*kt+1][1]);
            pa[3] = pack2(sacc[2*kt+1][2], sacc[2*kt+1][3]);
            pl[0] = pack2(lo_of(sacc[2*kt][0]),   lo_of(sacc[2*kt][1]));
            pl[1] = pack2(lo_of(sacc[2*kt][2]),   lo_of(sacc[2*kt][3]));
            pl[2] = pack2(lo_of(sacc[2*kt+1][0]), lo_of(sacc[2*kt+1][1]));
            pl[3] = pack2(lo_of(sacc[2*kt+1][2]), lo_of(sacc[2*kt+1][3]));
            #pragma unroll
            for (int dt = 0; dt < 8; dt++) {
                int w = (dt*8 + lr)*FW + kt*8 + c;
                uint32_t vb0 = Vsh32[w], vb1 = Vsh32[w + 4];
                uint32_t wl0 = Vsl32[w], wl1 = Vsl32[w + 4];
                mma_bf16(O[dt], pa[0], pa[1], pa[2], pa[3], vb0, vb1);
                mma_bf16(O[dt], pa[0], pa[1], pa[2], pa[3], wl0, wl1);
                mma_bf16(O[dt], pl[0], pl[1], pl[2], pl[3], vb0, vb1);
            }
        }
        __syncthreads();
    }

    // ---- finalize: /= l, write to g_attn [b, n, h*64 + d]
    const int b = bh >> 4;
    const int h = bh & 15;
    float inv0 = 1.0f / l0;
    float inv1 = 1.0f / l1;
    int row0 = q0 + wid*16 + lr;
    #pragma unroll
    for (int dt = 0; dt < 8; dt++) {
        int d = dt*8 + 2*c;
        size_t r0 = ((size_t)(b*NSEQ + row0))*BDIM + h*HD + d;
        *(float2*)&g_attn[r0]           = make_float2(O[dt][0]*inv0, O[dt][1]*inv0);
        *(float2*)&g_attn[r0 + 8*BDIM]  = make_float2(O[dt][2]*inv1, O[dt][3]*inv1);
    }
}

// =============================================================================
// Launch. Binding: size-classified (order-robust, verified in round 4).
// =============================================================================
extern "C" void kernel_launch(void* const* d_in, const int* in_sizes, int n_in,
                              void* d_out, int out_size)
{
    const float* big[3]  = {0,0,0};
    const float* Ws[4]   = {0,0,0,0};
    const float* bs[4]   = {0,0,0,0};
    int nbig = 0, nW = 0, nb = 0;
    for (int i = 0; i < n_in; i++) {
        int s = in_sizes[i];
        if (s == MROWS*BDIM)      { if (nbig < 3) big[nbig++] = (const float*)d_in[i]; }
        else if (s == BDIM*BDIM)  { if (nW  < 4) Ws[nW++]   = (const float*)d_in[i]; }
        else if (s == BDIM)       { if (nb  < 4) bs[nb++]   = (const float*)d_in[i]; }
    }
    const float* query = big[0];
    const float* key   = big[1];
    const float* value = big[2];
    const float* Wq = Ws[0]; const float* bq = bs[0];
    const float* Wk = Ws[1]; const float* bk = bs[1];
    const float* Wv = Ws[2]; const float* bv = bs[2];
    const float* Wo = Ws[3]; const float* bo = bs[3];

    void *qh, *ql, *kh, *kl, *vh, *vl;
    float* ab;
    cudaGetSymbolAddress(&qh, g_qh);
    cudaGetSymbolAddress(&ql, g_ql);
    cudaGetSymbolAddress(&kh, g_kh);
    cudaGetSymbolAddress(&kl, g_kl);
    cudaGetSymbolAddress(&vh, g_vh);
    cudaGetSymbolAddress(&vl, g_vl);
    cudaGetSymbolAddress((void**)&ab, g_attn);

    dim3 pg(BDIM/128, MROWS/128);   // (8, 72)
    proj_mma3<2><<<pg, 256>>>(query, Wq, bq, qh, ql);    // Q: rope + packed
    proj_mma3<2><<<pg, 256>>>(key,   Wk, bk, kh, kl);    // K: rope + packed
    proj_mma3<3><<<pg, 256>>>(value, Wv, bv, vh, vl);    // V: packed

    flash_kernel<<<dim3(NSEQ/128, NB*NH), 256>>>();

    proj_mma3<0><<<pg, 256>>>(ab, Wo, bo, d_out, nullptr);
}

// round 15
// speedup vs baseline: 1.2584x; 1.1292x over previous
#include <cuda_runtime.h>
#include <cuda_bf16.h>
#include <stdint.h>
#include <string.h>

// Problem constants
#define BDIM   1024
#define NSEQ   2304
#define NB     4
#define NH     16
#define HD     64
#define MROWS  (NB*NSEQ)      // 9216
#define HPATCH 48

// ---------------- scratch (static device globals; no allocation) -------------
// packed bf16 pair buffers: [bh][n][32 words], word w = (d=2w, d=2w+1)
__device__ uint32_t g_qh[(size_t)NB*NH*NSEQ*32];
__device__ uint32_t g_ql[(size_t)NB*NH*NSEQ*32];
__device__ uint32_t g_kh[(size_t)NB*NH*NSEQ*32];
__device__ uint32_t g_kl[(size_t)NB*NH*NSEQ*32];
__device__ uint32_t g_vh[(size_t)NB*NH*NSEQ*32];
__device__ uint32_t g_vl[(size_t)NB*NH*NSEQ*32];
__device__ float    g_attn[(size_t)NB*NSEQ*BDIM];    // [b,n,D]

// ---------------- bf16 helpers -----------------------------------------------
__device__ __forceinline__ uint32_t pack2(float a, float b) {
    __nv_bfloat16 ha = __float2bfloat16_rn(a);
    __nv_bfloat16 hb = __float2bfloat16_rn(b);
    uint16_t ra, rb;
    memcpy(&ra, &ha, 2); memcpy(&rb, &hb, 2);
    return (uint32_t)ra | ((uint32_t)rb << 16);
}
__device__ __forceinline__ float lo_of(float x) {
    return x - __bfloat162float(__float2bfloat16_rn(x));
}
__device__ __forceinline__ float ex2_approx(float x) {
    float r;
    asm("ex2.approx.ftz.f32 %0, %1;" : "=f"(r) : "f"(x));
    return r;
}

__device__ __forceinline__ void mma_bf16(float acc[4],
    uint32_t a0, uint32_t a1, uint32_t a2, uint32_t a3,
    uint32_t b0, uint32_t b1)
{
    asm volatile(
        "mma.sync.aligned.m16n8k16.row.col.f32.bf16.bf16.f32 "
        "{%0,%1,%2,%3}, {%4,%5,%6,%7}, {%8,%9}, {%0,%1,%2,%3};"
        : "+f"(acc[0]), "+f"(acc[1]), "+f"(acc[2]), "+f"(acc[3])
        : "r"(a0), "r"(a1), "r"(a2), "r"(a3), "r"(b0), "r"(b1));
}

// =============================================================================
// Projection GEMM (bf16x3): C[m][n] = sum_k X[m][k]*W[n][k] + bias[n]
// 128x128 block, 256 threads, BK=32, warp tile 64x32, 20-word smem row stride.
// Epilogue by MODE:
//   MODE 0: flat fp32 out [m][n]                           (output projection)
//   MODE 2: RoPE + packed bf16 hi/lo to (outA, outB)       (Q, K)
//   MODE 3: packed bf16 hi/lo to (outA, outB), no rope     (V)
// (verified round 14)
// =============================================================================
template<int MODE>
__global__ __launch_bounds__(256, 2)
void proj_mma3(const float* __restrict__ X, const float* __restrict__ W,
               const float* __restrict__ bias, void* outA, void* outB)
{
    __shared__ uint32_t Xh32[128*20], Xl32[128*20];
    __shared__ uint32_t Wh32[128*20], Wl32[128*20];

    const int tid   = threadIdx.x;
    const int lane  = tid & 31;
    const int wid   = tid >> 5;
    const int warpM = wid & 1;
    const int warpN = wid >> 1;
    const int c     = lane & 3;
    const int lr    = lane >> 2;
    const int m0 = blockIdx.y * 128;
    const int n0 = blockIdx.x * 128;

    float acc[4][4][4];
    #pragma unroll
    for (int a = 0; a < 4; a++)
        #pragma unroll
        for (int b = 0; b < 4; b++)
            #pragma unroll
            for (int d = 0; d < 4; d++) acc[a][b][d] = 0.f;

    for (int k0 = 0; k0 < BDIM; k0 += 32) {
        __syncthreads();
        #pragma unroll
        for (int s = 0; s < 4; s++) {
            int idx = tid + s*256;            // 0..1023 float4 ids (128 x 8)
            int r   = idx >> 3;
            int kq  = (idx & 7) * 4;
            int w0  = r*20 + (kq >> 1);
            float4 xa = *(const float4*)&X[(size_t)(m0+r)*BDIM + k0 + kq];
            Xh32[w0    ] = pack2(xa.x, xa.y);
            Xh32[w0 + 1] = pack2(xa.z, xa.w);
            Xl32[w0    ] = pack2(lo_of(xa.x), lo_of(xa.y));
            Xl32[w0 + 1] = pack2(lo_of(xa.z), lo_of(xa.w));
            float4 wb = *(const float4*)&W[(size_t)(n0+r)*BDIM + k0 + kq];
            Wh32[w0    ] = pack2(wb.x, wb.y);
            Wh32[w0 + 1] = pack2(wb.z, wb.w);
            Wl32[w0    ] = pack2(lo_of(wb.x), lo_of(wb.y));
            Wl32[w0 + 1] = pack2(lo_of(wb.z), lo_of(wb.w));
        }
        __syncthreads();

        #pragma unroll
        for (int kt = 0; kt < 2; kt++) {
            uint32_t ah[4][4], al[4][4];
            #pragma unroll
            for (int mt = 0; mt < 4; mt++) {
                int rA = warpM*64 + mt*16 + lr;
                int w  = rA*20 + kt*8 + c;
                ah[mt][0] = Xh32[w];        ah[mt][1] = Xh32[w + 8*20];
                ah[mt][2] = Xh32[w + 4];    ah[mt][3] = Xh32[w + 8*20 + 4];
                al[mt][0] = Xl32[w];        al[mt][1] = Xl32[w + 8*20];
                al[mt][2] = Xl32[w + 4];    al[mt][3] = Xl32[w + 8*20 + 4];
            }
            uint32_t bh[4][2], bl[4][2];
            #pragma unroll
            for (int nt = 0; nt < 4; nt++) {
                int nB = warpN*32 + nt*8 + lr;
                int w  = nB*20 + kt*8 + c;
                bh[nt][0] = Wh32[w];  bh[nt][1] = Wh32[w + 4];
                bl[nt][0] = Wl32[w];  bl[nt][1] = Wl32[w + 4];
            }
            #pragma unroll
            for (int mt = 0; mt < 4; mt++)
                #pragma unroll
                for (int nt = 0; nt < 4; nt++) {
                    mma_bf16(acc[mt][nt], ah[mt][0], ah[mt][1], ah[mt][2], ah[mt][3],
                             bh[nt][0], bh[nt][1]);
                    mma_bf16(acc[mt][nt], ah[mt][0], ah[mt][1], ah[mt][2], ah[mt][3],
                             bl[nt][0], bl[nt][1]);
                    mma_bf16(acc[mt][nt], al[mt][0], al[mt][1], al[mt][2], al[mt][3],
                             bh[nt][0], bh[nt][1]);
                }
        }
    }

    if (MODE == 0) {
        float* out = (float*)outA;
        #pragma unroll
        for (int mt = 0; mt < 4; mt++) {
            int m = m0 + warpM*64 + mt*16 + lr;
            #pragma unroll
            for (int nt = 0; nt < 4; nt++) {
                int n = n0 + warpN*32 + nt*8 + 2*c;
                float b0v = __ldg(&bias[n]);
                float b1v = __ldg(&bias[n+1]);
                *(float2*)&out[(size_t)m*BDIM + n] =
                    make_float2(acc[mt][nt][0] + b0v, acc[mt][nt][1] + b1v);
                *(float2*)&out[(size_t)(m+8)*BDIM + n] =
                    make_float2(acc[mt][nt][2] + b0v, acc[mt][nt][3] + b1v);
            }
        }
    } else {
        uint32_t* outh = (uint32_t*)outA;
        uint32_t* outl = (uint32_t*)outB;
        const int seg  = warpN & 1;
        const int head = (n0 + warpN*32) >> 6;
        #pragma unroll
        for (int mt = 0; mt < 4; mt++) {
            int m = m0 + warpM*64 + mt*16 + lr;
            int b = m / NSEQ;                 // tile never crosses batch
            int nseq = m - b*NSEQ;
            #pragma unroll
            for (int rh = 0; rh < 2; rh++) {
                int tok = nseq + rh*8;
                float vrot[4][2];
                if (MODE == 2) {
                    float pos = seg ? (float)(tok % HPATCH) : (float)(tok / HPATCH);
                    #pragma unroll
                    for (int nt01 = 0; nt01 < 2; nt01++)
                        #pragma unroll
                        for (int e = 0; e < 2; e++) {
                            int j = nt01*8 + 2*c + e;       // 0..15
                            float freq = powf(10000.0f, -(float)j / 16.0f);
                            float ang  = pos * freq;
                            float cc = cosf(ang);
                            float ss = sinf(ang);
                            int n1 = n0 + warpN*32 + j;
                            float x1 = acc[mt][nt01][e + 2*rh]   + __ldg(&bias[n1]);
                            float x2 = acc[mt][nt01+2][e + 2*rh] + __ldg(&bias[n1+16]);
                            vrot[nt01][e]   = x1*cc - x2*ss;
                            vrot[nt01+2][e] = x1*ss + x2*cc;
                        }
                } else {
                    #pragma unroll
                    for (int nt = 0; nt < 4; nt++) {
                        int n = n0 + warpN*32 + nt*8 + 2*c;
                        vrot[nt][0] = acc[mt][nt][0 + 2*rh] + __ldg(&bias[n]);
                        vrot[nt][1] = acc[mt][nt][1 + 2*rh] + __ldg(&bias[n+1]);
                    }
                }
                size_t rowbase = (((size_t)(b*NH + head))*NSEQ + tok)*32
                               + (size_t)seg*16;
                #pragma unroll
                for (int nt = 0; nt < 4; nt++) {
                    outh[rowbase + nt*4 + c] = pack2(vrot[nt][0], vrot[nt][1]);
                    outl[rowbase + nt*4 + c] = pack2(lo_of(vrot[nt][0]),
                                                     lo_of(vrot[nt][1]));
                }
            }
        }
    }
}

// =============================================================================
// Flash attention (bf16x3 mma, log2-domain online softmax).
// R14 arithmetic verbatim; occupancy fix: Q fragments live in a PERSISTENT
// dedicated smem region (not registers), __launch_bounds__(256,2) -> 2 CTAs/SM.
// Dynamic smem layout (words):
//   [0,      4608)  Qh   (128 rows x 36)
//   [4608,   9216)  Ql
//   [9216,  11520)  Ksh  (64 rows x 36)
//   [11520, 13824)  Ksl
//   [13824, 16128)  Vsh  (64 d-rows x 36)
//   [16128, 18432)  Vsl
// Total 73728 bytes; 2 CTAs = 147456 < 228K.
// =============================================================================
#define FW 36            // row stride in words for Q / K / V^T
#define QSC  0.18033688011112042f   // 0.125 * log2(e)
#define FL_SMEM (18432*4)

__global__ __launch_bounds__(256, 2)
void flash_kernel()
{
    extern __shared__ uint32_t dsm[];
    uint32_t* Qh32  = dsm;
    uint32_t* Ql32  = dsm + 4608;
    uint32_t* Ksh32 = dsm + 9216;
    uint32_t* Ksl32 = dsm + 11520;
    uint32_t* Vsh32 = dsm + 13824;
    uint32_t* Vsl32 = dsm + 16128;
    uint16_t* Vsh16 = (uint16_t*)Vsh32;
    uint16_t* Vsl16 = (uint16_t*)Vsl32;

    const int tid  = threadIdx.x;
    const int lane = tid & 31;
    const int wid  = tid >> 5;
    const int c    = lane & 3;
    const int lr   = lane >> 2;
    const int q0   = blockIdx.x * 128;
    const int bh   = blockIdx.y;

    const uint4* qhp = (const uint4*)(g_qh + (size_t)bh*NSEQ*32);
    const uint4* qlp = (const uint4*)(g_ql + (size_t)bh*NSEQ*32);
    const uint4* khp = (const uint4*)(g_kh + (size_t)bh*NSEQ*32);
    const uint4* klp = (const uint4*)(g_kl + (size_t)bh*NSEQ*32);
    const uint4* vhp = (const uint4*)(g_vh + (size_t)bh*NSEQ*32);
    const uint4* vlp = (const uint4*)(g_vl + (size_t)bh*NSEQ*32);

    // ---- stage Q once into the persistent region
    #pragma unroll
    for (int s = 0; s < 4; s++) {
        int idx = tid + s*256;                 // 0..1023 uint4 ids (128 x 8)
        int r   = idx >> 3;
        int qq  = idx & 7;
        *(uint4*)&Qh32[r*FW + qq*4] = qhp[(size_t)(q0+r)*8 + qq];
        *(uint4*)&Ql32[r*FW + qq*4] = qlp[(size_t)(q0+r)*8 + qq];
    }
    __syncthreads();

    const int rA = wid*16 + lr;                // this thread's Q fragment row

    float m0r = -__int_as_float(0x7f800000), m1r = m0r;   // -inf (log2 units)
    float l0 = 0.f, l1 = 0.f;
    float O[8][4];
    #pragma unroll
    for (int dt = 0; dt < 8; dt++)
        #pragma unroll
        for (int j = 0; j < 4; j++) O[dt][j] = 0.f;

    for (int kv0 = 0; kv0 < NSEQ; kv0 += 64) {
        // ---- K: straight packed copies (row kv, 8 uint4 each)
        #pragma unroll
        for (int s = 0; s < 2; s++) {
            int idx = tid + s*256;             // 0..511 uint4 ids (64 x 8)
            int kv  = idx >> 3;
            int qq  = idx & 7;
            *(uint4*)&Ksh32[kv*FW + qq*4] = khp[(size_t)(kv0+kv)*8 + qq];
            *(uint4*)&Ksl32[kv*FW + qq*4] = klp[(size_t)(kv0+kv)*8 + qq];
        }
        // ---- V: packed load + transpose store (d-major rows, scalar bf16)
        #pragma unroll
        for (int s = 0; s < 2; s++) {
            int idx = tid + s*256;             // 0..511
            int kv  = idx >> 3;
            int qq  = idx & 7;
            uint4 vh4 = vhp[(size_t)(kv0+kv)*8 + qq];
            uint4 vl4 = vlp[(size_t)(kv0+kv)*8 + qq];
            int d0 = qq*8;
            Vsh16[(d0+0)*72+kv] = (uint16_t)(vh4.x);
            Vsh16[(d0+1)*72+kv] = (uint16_t)(vh4.x >> 16);
            Vsh16[(d0+2)*72+kv] = (uint16_t)(vh4.y);
            Vsh16[(d0+3)*72+kv] = (uint16_t)(vh4.y >> 16);
            Vsh16[(d0+4)*72+kv] = (uint16_t)(vh4.z);
            Vsh16[(d0+5)*72+kv] = (uint16_t)(vh4.z >> 16);
            Vsh16[(d0+6)*72+kv] = (uint16_t)(vh4.w);
            Vsh16[(d0+7)*72+kv] = (uint16_t)(vh4.w >> 16);
            Vsl16[(d0+0)*72+kv] = (uint16_t)(vl4.x);
            Vsl16[(d0+1)*72+kv] = (uint16_t)(vl4.x >> 16);
            Vsl16[(d0+2)*72+kv] = (uint16_t)(vl4.y);
            Vsl16[(d0+3)*72+kv] = (uint16_t)(vl4.y >> 16);
            Vsl16[(d0+4)*72+kv] = (uint16_t)(vl4.z);
            Vsl16[(d0+5)*72+kv] = (uint16_t)(vl4.z >> 16);
            Vsl16[(d0+6)*72+kv] = (uint16_t)(vl4.w);
            Vsl16[(d0+7)*72+kv] = (uint16_t)(vl4.w >> 16);
        }
        __syncthreads();

        // ---- S = Q K^T (bf16x3), fp32 accum; Q fragments from smem per kt
        float sacc[8][4];
        #pragma unroll
        for (int nt = 0; nt < 8; nt++)
            #pragma unroll
            for (int j = 0; j < 4; j++) sacc[nt][j] = 0.f;

        #pragma unroll
        for (int kt = 0; kt < 4; kt++) {
            int wq = rA*FW + kt*8 + c;
            uint32_t qh0 = Qh32[wq],     qh1 = Qh32[wq + 8*FW];
            uint32_t qh2 = Qh32[wq + 4], qh3 = Qh32[wq + 8*FW + 4];
            uint32_t ql0 = Ql32[wq],     ql1 = Ql32[wq + 8*FW];
            uint32_t ql2 = Ql32[wq + 4], ql3 = Ql32[wq + 8*FW + 4];
            #pragma unroll
            for (int nt = 0; nt < 8; nt++) {
                int w  = (nt*8 + lr)*FW + kt*8 + c;
                uint32_t kb0 = Ksh32[w], kb1 = Ksh32[w + 4];
                uint32_t lb0 = Ksl32[w], lb1 = Ksl32[w + 4];
                mma_bf16(sacc[nt], qh0, qh1, qh2, qh3, kb0, kb1);
                mma_bf16(sacc[nt], qh0, qh1, qh2, qh3, lb0, lb1);
                mma_bf16(sacc[nt], ql0, ql1, ql2, ql3, kb0, kb1);
            }
        }

        // ---- scale to log2 units
        #pragma unroll
        for (int nt = 0; nt < 8; nt++)
            #pragma unroll
            for (int j = 0; j < 4; j++) sacc[nt][j] *= QSC;

        // ---- online softmax (rows r=lr and r+8; quad = lanes sharing lr)
        float mx0 = -__int_as_float(0x7f800000), mx1 = mx0;
        #pragma unroll
        for (int nt = 0; nt < 8; nt++) {
            mx0 = fmaxf(mx0, fmaxf(sacc[nt][0], sacc[nt][1]));
            mx1 = fmaxf(mx1, fmaxf(sacc[nt][2], sacc[nt][3]));
        }
        mx0 = fmaxf(mx0, __shfl_xor_sync(0xffffffffu, mx0, 1));
        mx0 = fmaxf(mx0, __shfl_xor_sync(0xffffffffu, mx0, 2));
        mx1 = fmaxf(mx1, __shfl_xor_sync(0xffffffffu, mx1, 1));
        mx1 = fmaxf(mx1, __shfl_xor_sync(0xffffffffu, mx1, 2));

        float mn0 = fmaxf(m0r, mx0);
        float mn1 = fmaxf(m1r, mx1);
        float cr0 = ex2_approx(m0r - mn0);
        float cr1 = ex2_approx(m1r - mn1);
        m0r = mn0; m1r = mn1;

        float rs0 = 0.f, rs1 = 0.f;
        #pragma unroll
        for (int nt = 0; nt < 8; nt++) {
            sacc[nt][0] = ex2_approx(sacc[nt][0] - mn0);
            sacc[nt][1] = ex2_approx(sacc[nt][1] - mn0);
            sacc[nt][2] = ex2_approx(sacc[nt][2] - mn1);
            sacc[nt][3] = ex2_approx(sacc[nt][3] - mn1);
            rs0 += sacc[nt][0] + sacc[nt][1];
            rs1 += sacc[nt][2] + sacc[nt][3];
        }
        rs0 += __shfl_xor_sync(0xffffffffu, rs0, 1);
        rs0 += __shfl_xor_sync(0xffffffffu, rs0, 2);
        rs1 += __shfl_xor_sync(0xffffffffu, rs1, 1);
        rs1 += __shfl_xor_sync(0xffffffffu, rs1, 2);
        l0 = l0 * cr0 + rs0;
        l1 = l1 * cr1 + rs1;

        #pragma unroll
        for (int dt = 0; dt < 8; dt++) {
            O[dt][0] *= cr0; O[dt][1] *= cr0;
            O[dt][2] *= cr1; O[dt][3] *= cr1;
        }

        // ---- O += P V (bf16x3); P from registers (S nt=2kt,2kt+1 -> A-frag kt)
        #pragma unroll
        for (int kt = 0; kt < 4; kt++) {
            uint32_t pa[4], pl[4];
            pa[0] = pack2(sacc[2*kt][0],   sacc[2*kt][1]);
            pa[1] = pack2(sacc[2*kt][2],   sacc[2*kt][3]);
            pa[2] = pack2(sacc[2*kt+1][0], sacc[2*kt+1][1]);
            pa[3] = pack2(sacc[2*kt+1][2], sacc[2*kt+1][3]);
            pl[0] = pack2(lo_of(sacc[2*kt][0]),   lo_of(sacc[2*kt][1]));
            pl[1] = pack2(lo_of(sacc[2*kt][2]),   lo_of(sacc[2*kt][3]));
            pl[2] = pack2(lo_of(sacc[2*kt+1][0]), lo_of(sacc[2*kt+1][1]));
            pl[3] = pack2(lo_of(sacc[2*kt+1][2]), lo_of(sacc[2*kt+1][3]));
            #pragma unroll
            for (int dt = 0; dt < 8; dt++) {
                int w = (dt*8 + lr)*FW + kt*8 + c;
                uint32_t vb0 = Vsh32[w], vb1 = Vsh32[w + 4];
                uint32_t wl0 = Vsl32[w], wl1 = Vsl32[w + 4];
                mma_bf16(O[dt], pa[0], pa[1], pa[2], pa[3], vb0, vb1);
                mma_bf16(O[dt], pa[0], pa[1], pa[2], pa[3], wl0, wl1);
                mma_bf16(O[dt], pl[0], pl[1], pl[2], pl[3], vb0, vb1);
            }
        }
        __syncthreads();
    }

    // ---- finalize: /= l, write to g_attn [b, n, h*64 + d]
    const int b = bh >> 4;
    const int h = bh & 15;
    float inv0 = 1.0f / l0;
    float inv1 = 1.0f / l1;
    int row0 = q0 + wid*16 + lr;
    #pragma unroll
    for (int dt = 0; dt < 8; dt++) {
        int d = dt*8 + 2*c;
        size_t r0 = ((size_t)(b*NSEQ + row0))*BDIM + h*HD + d;
        *(float2*)&g_attn[r0]           = make_float2(O[dt][0]*inv0, O[dt][1]*inv0);
        *(float2*)&g_attn[r0 + 8*BDIM]  = make_float2(O[dt][2]*inv1, O[dt][3]*inv1);
    }
}

// =============================================================================
// Launch. Binding: size-classified (order-robust, verified in round 4).
// =============================================================================
extern "C" void kernel_launch(void* const* d_in, const int* in_sizes, int n_in,
                              void* d_out, int out_size)
{
    const float* big[3]  = {0,0,0};
    const float* Ws[4]   = {0,0,0,0};
    const float* bs[4]   = {0,0,0,0};
    int nbig = 0, nW = 0, nb = 0;
    for (int i = 0; i < n_in; i++) {
        int s = in_sizes[i];
        if (s == MROWS*BDIM)      { if (nbig < 3) big[nbig++] = (const float*)d_in[i]; }
        else if (s == BDIM*BDIM)  { if (nW  < 4) Ws[nW++]   = (const float*)d_in[i]; }
        else if (s == BDIM)       { if (nb  < 4) bs[nb++]   = (const float*)d_in[i]; }
    }
    const float* query = big[0];
    const float* key   = big[1];
    const float* value = big[2];
    const float* Wq = Ws[0]; const float* bq = bs[0];
    const float* Wk = Ws[1]; const float* bk = bs[1];
    const float* Wv = Ws[2]; const float* bv = bs[2];
    const float* Wo = Ws[3]; const float* bo = bs[3];

    void *qh, *ql, *kh, *kl, *vh, *vl;
    float* ab;
    cudaGetSymbolAddress(&qh, g_qh);
    cudaGetSymbolAddress(&ql, g_ql);
    cudaGetSymbolAddress(&kh, g_kh);
    cudaGetSymbolAddress(&kl, g_kl);
    cudaGetSymbolAddress(&vh, g_vh);
    cudaGetSymbolAddress(&vl, g_vl);
    cudaGetSymbolAddress((void**)&ab, g_attn);

    cudaFuncSetAttribute(flash_kernel,
                         cudaFuncAttributeMaxDynamicSharedMemorySize, FL_SMEM);

    dim3 pg(BDIM/128, MROWS/128);   // (8, 72)
    proj_mma3<2><<<pg, 256>>>(query, Wq, bq, qh, ql);    // Q: rope + packed
    proj_mma3<2><<<pg, 256>>>(key,   Wk, bk, kh, kl);    // K: rope + packed
    proj_mma3<3><<<pg, 256>>>(value, Wv, bv, vh, vl);    // V: packed

    flash_kernel<<<dim3(NSEQ/128, NB*NH), 256, FL_SMEM>>>();

    proj_mma3<0><<<pg, 256>>>(ab, Wo, bo, d_out, nullptr);
}

// round 16
// speedup vs baseline: 1.5278x; 1.2141x over previous
#include <cuda_runtime.h>
#include <cuda_bf16.h>
#include <stdint.h>
#include <string.h>

// Problem constants
#define BDIM   1024
#define NSEQ   2304
#define NB     4
#define NH     16
#define HD     64
#define MROWS  (NB*NSEQ)      // 9216
#define HPATCH 48

// ---------------- scratch (static device globals; no allocation) -------------
// packed bf16 pair buffers: [bh][n][32 words], word w = (d=2w, d=2w+1)
__device__ uint32_t g_qh[(size_t)NB*NH*NSEQ*32];
__device__ uint32_t g_ql[(size_t)NB*NH*NSEQ*32];
__device__ uint32_t g_kh[(size_t)NB*NH*NSEQ*32];
__device__ uint32_t g_kl[(size_t)NB*NH*NSEQ*32];
__device__ uint32_t g_vh[(size_t)NB*NH*NSEQ*32];
__device__ uint32_t g_vl[(size_t)NB*NH*NSEQ*32];
__device__ float    g_attn[(size_t)NB*NSEQ*BDIM];    // [b,n,D]

// ---------------- bf16 helpers -----------------------------------------------
__device__ __forceinline__ uint32_t pack2(float a, float b) {
    __nv_bfloat16 ha = __float2bfloat16_rn(a);
    __nv_bfloat16 hb = __float2bfloat16_rn(b);
    uint16_t ra, rb;
    memcpy(&ra, &ha, 2); memcpy(&rb, &hb, 2);
    return (uint32_t)ra | ((uint32_t)rb << 16);
}
__device__ __forceinline__ float lo_of(float x) {
    return x - __bfloat162float(__float2bfloat16_rn(x));
}
__device__ __forceinline__ float ex2_approx(float x) {
    float r;
    asm("ex2.approx.ftz.f32 %0, %1;" : "=f"(r) : "f"(x));
    return r;
}

__device__ __forceinline__ void mma_bf16(float acc[4],
    uint32_t a0, uint32_t a1, uint32_t a2, uint32_t a3,
    uint32_t b0, uint32_t b1)
{
    asm volatile(
        "mma.sync.aligned.m16n8k16.row.col.f32.bf16.bf16.f32 "
        "{%0,%1,%2,%3}, {%4,%5,%6,%7}, {%8,%9}, {%0,%1,%2,%3};"
        : "+f"(acc[0]), "+f"(acc[1]), "+f"(acc[2]), "+f"(acc[3])
        : "r"(a0), "r"(a1), "r"(a2), "r"(a3), "r"(b0), "r"(b1));
}

__device__ __forceinline__ void ldsm_x4(uint32_t& r0, uint32_t& r1,
                                        uint32_t& r2, uint32_t& r3,
                                        const uint32_t* p)
{
    uint32_t a = (uint32_t)__cvta_generic_to_shared(p);
    asm volatile("ldmatrix.sync.aligned.m8n8.x4.shared.b16 {%0,%1,%2,%3}, [%4];"
                 : "=r"(r0), "=r"(r1), "=r"(r2), "=r"(r3) : "r"(a));
}
__device__ __forceinline__ void ldsm_x4_t(uint32_t& r0, uint32_t& r1,
                                          uint32_t& r2, uint32_t& r3,
                                          const uint32_t* p)
{
    uint32_t a = (uint32_t)__cvta_generic_to_shared(p);
    asm volatile("ldmatrix.sync.aligned.m8n8.x4.trans.shared.b16 {%0,%1,%2,%3}, [%4];"
                 : "=r"(r0), "=r"(r1), "=r"(r2), "=r"(r3) : "r"(a));
}

// =============================================================================
// Projection GEMM (bf16x3): verified round 14, kept verbatim.
//   MODE 0: flat fp32 out [m][n]; MODE 2: RoPE + packed hi/lo; MODE 3: packed.
// =============================================================================
template<int MODE>
__global__ __launch_bounds__(256, 2)
void proj_mma3(const float* __restrict__ X, const float* __restrict__ W,
               const float* __restrict__ bias, void* outA, void* outB)
{
    __shared__ uint32_t Xh32[128*20], Xl32[128*20];
    __shared__ uint32_t Wh32[128*20], Wl32[128*20];

    const int tid   = threadIdx.x;
    const int lane  = tid & 31;
    const int wid   = tid >> 5;
    const int warpM = wid & 1;
    const int warpN = wid >> 1;
    const int c     = lane & 3;
    const int lr    = lane >> 2;
    const int m0 = blockIdx.y * 128;
    const int n0 = blockIdx.x * 128;

    float acc[4][4][4];
    #pragma unroll
    for (int a = 0; a < 4; a++)
        #pragma unroll
        for (int b = 0; b < 4; b++)
            #pragma unroll
            for (int d = 0; d < 4; d++) acc[a][b][d] = 0.f;

    for (int k0 = 0; k0 < BDIM; k0 += 32) {
        __syncthreads();
        #pragma unroll
        for (int s = 0; s < 4; s++) {
            int idx = tid + s*256;            // 0..1023 float4 ids (128 x 8)
            int r   = idx >> 3;
            int kq  = (idx & 7) * 4;
            int w0  = r*20 + (kq >> 1);
            float4 xa = *(const float4*)&X[(size_t)(m0+r)*BDIM + k0 + kq];
            Xh32[w0    ] = pack2(xa.x, xa.y);
            Xh32[w0 + 1] = pack2(xa.z, xa.w);
            Xl32[w0    ] = pack2(lo_of(xa.x), lo_of(xa.y));
            Xl32[w0 + 1] = pack2(lo_of(xa.z), lo_of(xa.w));
            float4 wb = *(const float4*)&W[(size_t)(n0+r)*BDIM + k0 + kq];
            Wh32[w0    ] = pack2(wb.x, wb.y);
            Wh32[w0 + 1] = pack2(wb.z, wb.w);
            Wl32[w0    ] = pack2(lo_of(wb.x), lo_of(wb.y));
            Wl32[w0 + 1] = pack2(lo_of(wb.z), lo_of(wb.w));
        }
        __syncthreads();

        #pragma unroll
        for (int kt = 0; kt < 2; kt++) {
            uint32_t ah[4][4], al[4][4];
            #pragma unroll
            for (int mt = 0; mt < 4; mt++) {
                int rA = warpM*64 + mt*16 + lr;
                int w  = rA*20 + kt*8 + c;
                ah[mt][0] = Xh32[w];        ah[mt][1] = Xh32[w + 8*20];
                ah[mt][2] = Xh32[w + 4];    ah[mt][3] = Xh32[w + 8*20 + 4];
                al[mt][0] = Xl32[w];        al[mt][1] = Xl32[w + 8*20];
                al[mt][2] = Xl32[w + 4];    al[mt][3] = Xl32[w + 8*20 + 4];
            }
            uint32_t bh[4][2], bl[4][2];
            #pragma unroll
            for (int nt = 0; nt < 4; nt++) {
                int nB = warpN*32 + nt*8 + lr;
                int w  = nB*20 + kt*8 + c;
                bh[nt][0] = Wh32[w];  bh[nt][1] = Wh32[w + 4];
                bl[nt][0] = Wl32[w];  bl[nt][1] = Wl32[w + 4];
            }
            #pragma unroll
            for (int mt = 0; mt < 4; mt++)
                #pragma unroll
                for (int nt = 0; nt < 4; nt++) {
                    mma_bf16(acc[mt][nt], ah[mt][0], ah[mt][1], ah[mt][2], ah[mt][3],
                             bh[nt][0], bh[nt][1]);
                    mma_bf16(acc[mt][nt], ah[mt][0], ah[mt][1], ah[mt][2], ah[mt][3],
                             bl[nt][0], bl[nt][1]);
                    mma_bf16(acc[mt][nt], al[mt][0], al[mt][1], al[mt][2], al[mt][3],
                             bh[nt][0], bh[nt][1]);
                }
        }
    }

    if (MODE == 0) {
        float* out = (float*)outA;
        #pragma unroll
        for (int mt = 0; mt < 4; mt++) {
            int m = m0 + warpM*64 + mt*16 + lr;
            #pragma unroll
            for (int nt = 0; nt < 4; nt++) {
                int n = n0 + warpN*32 + nt*8 + 2*c;
                float b0v = __ldg(&bias[n]);
                float b1v = __ldg(&bias[n+1]);
                *(float2*)&out[(size_t)m*BDIM + n] =
                    make_float2(acc[mt][nt][0] + b0v, acc[mt][nt][1] + b1v);
                *(float2*)&out[(size_t)(m+8)*BDIM + n] =
                    make_float2(acc[mt][nt][2] + b0v, acc[mt][nt][3] + b1v);
            }
        }
    } else {
        uint32_t* outh = (uint32_t*)outA;
        uint32_t* outl = (uint32_t*)outB;
        const int seg  = warpN & 1;
        const int head = (n0 + warpN*32) >> 6;
        #pragma unroll
        for (int mt = 0; mt < 4; mt++) {
            int m = m0 + warpM*64 + mt*16 + lr;
            int b = m / NSEQ;                 // tile never crosses batch
            int nseq = m - b*NSEQ;
            #pragma unroll
            for (int rh = 0; rh < 2; rh++) {
                int tok = nseq + rh*8;
                float vrot[4][2];
                if (MODE == 2) {
                    float pos = seg ? (float)(tok % HPATCH) : (float)(tok / HPATCH);
                    #pragma unroll
                    for (int nt01 = 0; nt01 < 2; nt01++)
                        #pragma unroll
                        for (int e = 0; e < 2; e++) {
                            int j = nt01*8 + 2*c + e;       // 0..15
                            float freq = powf(10000.0f, -(float)j / 16.0f);
                            float ang  = pos * freq;
                            float cc = cosf(ang);
                            float ss = sinf(ang);
                            int n1 = n0 + warpN*32 + j;
                            float x1 = acc[mt][nt01][e + 2*rh]   + __ldg(&bias[n1]);
                            float x2 = acc[mt][nt01+2][e + 2*rh] + __ldg(&bias[n1+16]);
                            vrot[nt01][e]   = x1*cc - x2*ss;
                            vrot[nt01+2][e] = x1*ss + x2*cc;
                        }
                } else {
                    #pragma unroll
                    for (int nt = 0; nt < 4; nt++) {
                        int n = n0 + warpN*32 + nt*8 + 2*c;
                        vrot[nt][0] = acc[mt][nt][0 + 2*rh] + __ldg(&bias[n]);
                        vrot[nt][1] = acc[mt][nt][1 + 2*rh] + __ldg(&bias[n+1]);
                    }
                }
                size_t rowbase = (((size_t)(b*NH + head))*NSEQ + tok)*32
                               + (size_t)seg*16;
                #pragma unroll
                for (int nt = 0; nt < 4; nt++) {
                    outh[rowbase + nt*4 + c] = pack2(vrot[nt][0], vrot[nt][1]);
                    outl[rowbase + nt*4 + c] = pack2(lo_of(vrot[nt][0]),
                                                     lo_of(vrot[nt][1]));
                }
            }
        }
    }
}

// =============================================================================
// Flash attention (bf16x3 mma). R15 arithmetic; all smem fragment traffic via
// ldmatrix (Q/K natural, V row-major + .trans), V transpose stores eliminated.
// Dynamic smem layout (words):
//   [0,      4608)  Qh   (128 rows x 36)
//   [4608,   9216)  Ql
//   [9216,  11520)  Ksh  (64 rows x 36)
//   [11520, 13824)  Ksl
//   [13824, 16128)  Vsh  (64 rows x 36, ROW-major like K)
//   [16128, 18432)  Vsl
// =============================================================================
#define FW 36            // row stride in words
#define QSC  0.18033688011112042f   // 0.125 * log2(e)
#define FL_SMEM (18432*4)

__global__ __launch_bounds__(256, 2)
void flash_kernel()
{
    extern __shared__ uint32_t dsm[];
    uint32_t* Qh32  = dsm;
    uint32_t* Ql32  = dsm + 4608;
    uint32_t* Ksh32 = dsm + 9216;
    uint32_t* Ksl32 = dsm + 11520;
    uint32_t* Vsh32 = dsm + 13824;
    uint32_t* Vsl32 = dsm + 16128;

    const int tid  = threadIdx.x;
    const int lane = tid & 31;
    const int wid  = tid >> 5;
    const int c    = lane & 3;
    const int lr   = lane >> 2;
    const int q0   = blockIdx.x * 128;
    const int bh   = blockIdx.y;

    // ldmatrix lane-address components (t = tile id 0..3, rt = row in tile)
    const int lt  = lane >> 3;        // tile id
    const int rt  = lane & 7;         // row within tile

    const uint4* qhp = (const uint4*)(g_qh + (size_t)bh*NSEQ*32);
    const uint4* qlp = (const uint4*)(g_ql + (size_t)bh*NSEQ*32);
    const uint4* khp = (const uint4*)(g_kh + (size_t)bh*NSEQ*32);
    const uint4* klp = (const uint4*)(g_kl + (size_t)bh*NSEQ*32);
    const uint4* vhp = (const uint4*)(g_vh + (size_t)bh*NSEQ*32);
    const uint4* vlp = (const uint4*)(g_vl + (size_t)bh*NSEQ*32);

    // ---- stage Q once
    #pragma unroll
    for (int s = 0; s < 4; s++) {
        int idx = tid + s*256;                 // 0..1023 uint4 ids (128 x 8)
        int r   = idx >> 3;
        int qq  = idx & 7;
        *(uint4*)&Qh32[r*FW + qq*4] = qhp[(size_t)(q0+r)*8 + qq];
        *(uint4*)&Ql32[r*FW + qq*4] = qlp[(size_t)(q0+r)*8 + qq];
    }
    __syncthreads();

    float m0r = -__int_as_float(0x7f800000), m1r = m0r;   // -inf (log2 units)
    float l0 = 0.f, l1 = 0.f;
    float O[8][4];
    #pragma unroll
    for (int dt = 0; dt < 8; dt++)
        #pragma unroll
        for (int j = 0; j < 4; j++) O[dt][j] = 0.f;

    for (int kv0 = 0; kv0 < NSEQ; kv0 += 64) {
        // ---- K and V: straight packed uint4 copies (row-major)
        #pragma unroll
        for (int s = 0; s < 2; s++) {
            int idx = tid + s*256;             // 0..511 uint4 ids (64 x 8)
            int kv  = idx >> 3;
            int qq  = idx & 7;
            *(uint4*)&Ksh32[kv*FW + qq*4] = khp[(size_t)(kv0+kv)*8 + qq];
            *(uint4*)&Ksl32[kv*FW + qq*4] = klp[(size_t)(kv0+kv)*8 + qq];
            *(uint4*)&Vsh32[kv*FW + qq*4] = vhp[(size_t)(kv0+kv)*8 + qq];
            *(uint4*)&Vsl32[kv*FW + qq*4] = vlp[(size_t)(kv0+kv)*8 + qq];
        }
        __syncthreads();

        // ---- S = Q K^T (bf16x3), fp32 accum
        float sacc[8][4];
        #pragma unroll
        for (int nt = 0; nt < 8; nt++)
            #pragma unroll
            for (int j = 0; j < 4; j++) sacc[nt][j] = 0.f;

        #pragma unroll
        for (int kt = 0; kt < 4; kt++) {
            // Q A-fragments: tiles (m-lo/hi, k-lo/hi)
            // lane addr: row = wid*16 + (lt&1)*8 + rt, colword = kt*8 + (lt>>1)*4
            uint32_t qh0, qh1, qh2, qh3, ql0, ql1, ql2, ql3;
            {
                int row = wid*16 + (lt & 1)*8 + rt;
                int cw  = kt*8 + (lt >> 1)*4;
                ldsm_x4(qh0, qh1, qh2, qh3, &Qh32[row*FW + cw]);
                ldsm_x4(ql0, ql1, ql2, ql3, &Ql32[row*FW + cw]);
            }
            // K B-fragments: 4 nt-pairs; tiles (nt + lt>>1, k-lo/hi by lt&1)
            #pragma unroll
            for (int p = 0; p < 4; p++) {
                int row = (2*p + (lt >> 1))*8 + rt;
                int cw  = kt*8 + (lt & 1)*4;
                uint32_t kb0, kb1, kb2, kb3, lb0, lb1, lb2, lb3;
                ldsm_x4(kb0, kb1, kb2, kb3, &Ksh32[row*FW + cw]);
                ldsm_x4(lb0, lb1, lb2, lb3, &Ksl32[row*FW + cw]);
                mma_bf16(sacc[2*p],   qh0, qh1, qh2, qh3, kb0, kb1);
                mma_bf16(sacc[2*p],   qh0, qh1, qh2, qh3, lb0, lb1);
                mma_bf16(sacc[2*p],   ql0, ql1, ql2, ql3, kb0, kb1);
                mma_bf16(sacc[2*p+1], qh0, qh1, qh2, qh3, kb2, kb3);
                mma_bf16(sacc[2*p+1], qh0, qh1, qh2, qh3, lb2, lb3);
                mma_bf16(sacc[2*p+1], ql0, ql1, ql2, ql3, kb2, kb3);
            }
        }

        // ---- scale to log2 units
        #pragma unroll
        for (int nt = 0; nt < 8; nt++)
            #pragma unroll
            for (int j = 0; j < 4; j++) sacc[nt][j] *= QSC;

        // ---- online softmax (rows r=lr and r+8; quad = lanes sharing lr)
        float mx0 = -__int_as_float(0x7f800000), mx1 = mx0;
        #pragma unroll
        for (int nt = 0; nt < 8; nt++) {
            mx0 = fmaxf(mx0, fmaxf(sacc[nt][0], sacc[nt][1]));
            mx1 = fmaxf(mx1, fmaxf(sacc[nt][2], sacc[nt][3]));
        }
        mx0 = fmaxf(mx0, __shfl_xor_sync(0xffffffffu, mx0, 1));
        mx0 = fmaxf(mx0, __shfl_xor_sync(0xffffffffu, mx0, 2));
        mx1 = fmaxf(mx1, __shfl_xor_sync(0xffffffffu, mx1, 1));
        mx1 = fmaxf(mx1, __shfl_xor_sync(0xffffffffu, mx1, 2));

        float mn0 = fmaxf(m0r, mx0);
        float mn1 = fmaxf(m1r, mx1);
        float cr0 = ex2_approx(m0r - mn0);
        float cr1 = ex2_approx(m1r - mn1);
        m0r = mn0; m1r = mn1;

        float rs0 = 0.f, rs1 = 0.f;
        #pragma unroll
        for (int nt = 0; nt < 8; nt++) {
            sacc[nt][0] = ex2_approx(sacc[nt][0] - mn0);
            sacc[nt][1] = ex2_approx(sacc[nt][1] - mn0);
            sacc[nt][2] = ex2_approx(sacc[nt][2] - mn1);
            sacc[nt][3] = ex2_approx(sacc[nt][3] - mn1);
            rs0 += sacc[nt][0] + sacc[nt][1];
            rs1 += sacc[nt][2] + sacc[nt][3];
        }
        rs0 += __shfl_xor_sync(0xffffffffu, rs0, 1);
        rs0 += __shfl_xor_sync(0xffffffffu, rs0, 2);
        rs1 += __shfl_xor_sync(0xffffffffu, rs1, 1);
        rs1 += __shfl_xor_sync(0xffffffffu, rs1, 2);
        l0 = l0 * cr0 + rs0;
        l1 = l1 * cr1 + rs1;

        #pragma unroll
        for (int dt = 0; dt < 8; dt++) {
            O[dt][0] *= cr0; O[dt][1] *= cr0;
            O[dt][2] *= cr1; O[dt][3] *= cr1;
        }

        // ---- O += P V (bf16x3); P from registers; V B-frags via ldmatrix.trans
        #pragma unroll
        for (int kt = 0; kt < 4; kt++) {
            uint32_t pa[4], pl[4];
            pa[0] = pack2(sacc[2*kt][0],   sacc[2*kt][1]);
            pa[1] = pack2(sacc[2*kt][2],   sacc[2*kt][3]);
            pa[2] = pack2(sacc[2*kt+1][0], sacc[2*kt+1][1]);
            pa[3] = pack2(sacc[2*kt+1][2], sacc[2*kt+1][3]);
            pl[0] = pack2(lo_of(sacc[2*kt][0]),   lo_of(sacc[2*kt][1]));
            pl[1] = pack2(lo_of(sacc[2*kt][2]),   lo_of(sacc[2*kt][3]));
            pl[2] = pack2(lo_of(sacc[2*kt+1][0]), lo_of(sacc[2*kt+1][1]));
            pl[3] = pack2(lo_of(sacc[2*kt+1][2]), lo_of(sacc[2*kt+1][3]));
            // V tiles (un-transposed): rows = kv (k), cols = d block.
            // pair p covers dt = 2p, 2p+1.
            // lane addr: row = kt*16 + (lt&1)*8 + rt, colword = (2p + lt>>1)*4
            #pragma unroll
            for (int p = 0; p < 4; p++) {
                int row = kt*16 + (lt & 1)*8 + rt;
                int cw  = (2*p + (lt >> 1))*4;
                uint32_t vb0, vb1, vb2, vb3, wl0, wl1, wl2, wl3;
                ldsm_x4_t(vb0, vb1, vb2, vb3, &Vsh32[row*FW + cw]);
                ldsm_x4_t(wl0, wl1, wl2, wl3, &Vsl32[row*FW + cw]);
                mma_bf16(O[2*p],   pa[0], pa[1], pa[2], pa[3], vb0, vb1);
                mma_bf16(O[2*p],   pa[0], pa[1], pa[2], pa[3], wl0, wl1);
                mma_bf16(O[2*p],   pl[0], pl[1], pl[2], pl[3], vb0, vb1);
                mma_bf16(O[2*p+1], pa[0], pa[1], pa[2], pa[3], vb2, vb3);
                mma_bf16(O[2*p+1], pa[0], pa[1], pa[2], pa[3], wl2, wl3);
                mma_bf16(O[2*p+1], pl[0], pl[1], pl[2], pl[3], vb2, vb3);
            }
        }
        __syncthreads();
    }

    // ---- finalize: /= l, write to g_attn [b, n, h*64 + d]
    const int b = bh >> 4;
    const int h = bh & 15;
    float inv0 = 1.0f / l0;
    float inv1 = 1.0f / l1;
    int row0 = q0 + wid*16 + lr;
    #pragma unroll
    for (int dt = 0; dt < 8; dt++) {
        int d = dt*8 + 2*c;
        size_t r0 = ((size_t)(b*NSEQ + row0))*BDIM + h*HD + d;
        *(float2*)&g_attn[r0]           = make_float2(O[dt][0]*inv0, O[dt][1]*inv0);
        *(float2*)&g_attn[r0 + 8*BDIM]  = make_float2(O[dt][2]*inv1, O[dt][3]*inv1);
    }
}

// =============================================================================
// Launch. Binding: size-classified (order-robust, verified in round 4).
// =============================================================================
extern "C" void kernel_launch(void* const* d_in, const int* in_sizes, int n_in,
                              void* d_out, int out_size)
{
    const float* big[3]  = {0,0,0};
    const float* Ws[4]   = {0,0,0,0};
    const float* bs[4]   = {0,0,0,0};
    int nbig = 0, nW = 0, nb = 0;
    for (int i = 0; i < n_in; i++) {
        int s = in_sizes[i];
        if (s == MROWS*BDIM)      { if (nbig < 3) big[nbig++] = (const float*)d_in[i]; }
        else if (s == BDIM*BDIM)  { if (nW  < 4) Ws[nW++]   = (const float*)d_in[i]; }
        else if (s == BDIM)       { if (nb  < 4) bs[nb++]   = (const float*)d_in[i]; }
    }
    const float* query = big[0];
    const float* key   = big[1];
    const float* value = big[2];
    const float* Wq = Ws[0]; const float* bq = bs[0];
    const float* Wk = Ws[1]; const float* bk = bs[1];
    const float* Wv = Ws[2]; const float* bv = bs[2];
    const float* Wo = Ws[3]; const float* bo = bs[3];

    void *qh, *ql, *kh, *kl, *vh, *vl;
    float* ab;
    cudaGetSymbolAddress(&qh, g_qh);
    cudaGetSymbolAddress(&ql, g_ql);
    cudaGetSymbolAddress(&kh, g_kh);
    cudaGetSymbolAddress(&kl, g_kl);
    cudaGetSymbolAddress(&vh, g_vh);
    cudaGetSymbolAddress(&vl, g_vl);
    cudaGetSymbolAddress((void**)&ab, g_attn);

    cudaFuncSetAttribute(flash_kernel,
                         cudaFuncAttributeMaxDynamicSharedMemorySize, FL_SMEM);

    dim3 pg(BDIM/128, MROWS/128);   // (8, 72)
    proj_mma3<2><<<pg, 256>>>(query, Wq, bq, qh, ql);    // Q: rope + packed
    proj_mma3<2><<<pg, 256>>>(key,   Wk, bk, kh, kl);    // K: rope + packed
    proj_mma3<3><<<pg, 256>>>(value, Wv, bv, vh, vl);    // V: packed

    flash_kernel<<<dim3(NSEQ/128, NB*NH), 256, FL_SMEM>>>();

    proj_mma3<0><<<pg, 256>>>(ab, Wo, bo, d_out, nullptr);
}

// round 17
// speedup vs baseline: 1.5737x; 1.0301x over previous
#include <cuda_runtime.h>
#include <cuda_bf16.h>
#include <stdint.h>
#include <string.h>

// Problem constants
#define BDIM   1024
#define NSEQ   2304
#define NB     4
#define NH     16
#define HD     64
#define MROWS  (NB*NSEQ)      // 9216
#define HPATCH 48

// ---------------- scratch (static device globals; no allocation) -------------
// packed bf16 pair buffers: [bh][n][32 words], word w = (d=2w, d=2w+1)
__device__ uint32_t g_qh[(size_t)NB*NH*NSEQ*32];
__device__ uint32_t g_ql[(size_t)NB*NH*NSEQ*32];
__device__ uint32_t g_kh[(size_t)NB*NH*NSEQ*32];
__device__ uint32_t g_kl[(size_t)NB*NH*NSEQ*32];
__device__ uint32_t g_vh[(size_t)NB*NH*NSEQ*32];
__device__ uint32_t g_vl[(size_t)NB*NH*NSEQ*32];
__device__ float    g_attn[(size_t)NB*NSEQ*BDIM];    // [b,n,D]

// ---------------- bf16 helpers -----------------------------------------------
__device__ __forceinline__ uint32_t pack2(float a, float b) {
    __nv_bfloat16 ha = __float2bfloat16_rn(a);
    __nv_bfloat16 hb = __float2bfloat16_rn(b);
    uint16_t ra, rb;
    memcpy(&ra, &ha, 2); memcpy(&rb, &hb, 2);
    return (uint32_t)ra | ((uint32_t)rb << 16);
}
__device__ __forceinline__ float lo_of(float x) {
    return x - __bfloat162float(__float2bfloat16_rn(x));
}
__device__ __forceinline__ float ex2_approx(float x) {
    float r;
    asm("ex2.approx.ftz.f32 %0, %1;" : "=f"(r) : "f"(x));
    return r;
}

__device__ __forceinline__ void mma_bf16(float acc[4],
    uint32_t a0, uint32_t a1, uint32_t a2, uint32_t a3,
    uint32_t b0, uint32_t b1)
{
    asm volatile(
        "mma.sync.aligned.m16n8k16.row.col.f32.bf16.bf16.f32 "
        "{%0,%1,%2,%3}, {%4,%5,%6,%7}, {%8,%9}, {%0,%1,%2,%3};"
        : "+f"(acc[0]), "+f"(acc[1]), "+f"(acc[2]), "+f"(acc[3])
        : "r"(a0), "r"(a1), "r"(a2), "r"(a3), "r"(b0), "r"(b1));
}

__device__ __forceinline__ void ldsm_x4(uint32_t& r0, uint32_t& r1,
                                        uint32_t& r2, uint32_t& r3,
                                        const uint32_t* p)
{
    uint32_t a = (uint32_t)__cvta_generic_to_shared(p);
    asm volatile("ldmatrix.sync.aligned.m8n8.x4.shared.b16 {%0,%1,%2,%3}, [%4];"
                 : "=r"(r0), "=r"(r1), "=r"(r2), "=r"(r3) : "r"(a));
}
__device__ __forceinline__ void ldsm_x4_t(uint32_t& r0, uint32_t& r1,
                                          uint32_t& r2, uint32_t& r3,
                                          const uint32_t* p)
{
    uint32_t a = (uint32_t)__cvta_generic_to_shared(p);
    asm volatile("ldmatrix.sync.aligned.m8n8.x4.trans.shared.b16 {%0,%1,%2,%3}, [%4];"
                 : "=r"(r0), "=r"(r1), "=r"(r2), "=r"(r3) : "r"(a));
}

// =============================================================================
// Projection GEMM (bf16x3): load/convert + epilogues verbatim round 14;
// fragment loads now via ldmatrix (A mapping = flash-Q, B mapping = flash-K,
// both HW-validated in round 16). 20-word row stride is LDSM-conflict-free
// (20r mod 32 distinct over 8 rows).
//   MODE 0: flat fp32 out [m][n]; MODE 2: RoPE + packed hi/lo; MODE 3: packed.
// =============================================================================
template<int MODE>
__global__ __launch_bounds__(256, 2)
void proj_mma3(const float* __restrict__ X, const float* __restrict__ W,
               const float* __restrict__ bias, void* outA, void* outB)
{
    __shared__ uint32_t Xh32[128*20], Xl32[128*20];
    __shared__ uint32_t Wh32[128*20], Wl32[128*20];

    const int tid   = threadIdx.x;
    const int lane  = tid & 31;
    const int wid   = tid >> 5;
    const int warpM = wid & 1;
    const int warpN = wid >> 1;
    const int c     = lane & 3;
    const int lr    = lane >> 2;
    const int lt    = lane >> 3;      // ldmatrix tile id
    const int rt    = lane & 7;       // ldmatrix row within tile
    const int m0 = blockIdx.y * 128;
    const int n0 = blockIdx.x * 128;

    float acc[4][4][4];
    #pragma unroll
    for (int a = 0; a < 4; a++)
        #pragma unroll
        for (int b = 0; b < 4; b++)
            #pragma unroll
            for (int d = 0; d < 4; d++) acc[a][b][d] = 0.f;

    for (int k0 = 0; k0 < BDIM; k0 += 32) {
        __syncthreads();
        #pragma unroll
        for (int s = 0; s < 4; s++) {
            int idx = tid + s*256;            // 0..1023 float4 ids (128 x 8)
            int r   = idx >> 3;
            int kq  = (idx & 7) * 4;
            int w0  = r*20 + (kq >> 1);
            float4 xa = *(const float4*)&X[(size_t)(m0+r)*BDIM + k0 + kq];
            Xh32[w0    ] = pack2(xa.x, xa.y);
            Xh32[w0 + 1] = pack2(xa.z, xa.w);
            Xl32[w0    ] = pack2(lo_of(xa.x), lo_of(xa.y));
            Xl32[w0 + 1] = pack2(lo_of(xa.z), lo_of(xa.w));
            float4 wb = *(const float4*)&W[(size_t)(n0+r)*BDIM + k0 + kq];
            Wh32[w0    ] = pack2(wb.x, wb.y);
            Wh32[w0 + 1] = pack2(wb.z, wb.w);
            Wl32[w0    ] = pack2(lo_of(wb.x), lo_of(wb.y));
            Wl32[w0 + 1] = pack2(lo_of(wb.z), lo_of(wb.w));
        }
        __syncthreads();

        #pragma unroll
        for (int kt = 0; kt < 2; kt++) {
            // A fragments via ldmatrix: row = warpM*64+mt*16+(lt&1)*8+rt,
            // colword = kt*8+(lt>>1)*4  (validated mapping)
            uint32_t ah[4][4], al[4][4];
            #pragma unroll
            for (int mt = 0; mt < 4; mt++) {
                int row = warpM*64 + mt*16 + (lt & 1)*8 + rt;
                int cw  = kt*8 + (lt >> 1)*4;
                ldsm_x4(ah[mt][0], ah[mt][1], ah[mt][2], ah[mt][3],
                        &Xh32[row*20 + cw]);
                ldsm_x4(al[mt][0], al[mt][1], al[mt][2], al[mt][3],
                        &Xl32[row*20 + cw]);
            }
            // B fragments via ldmatrix pairs: nt in {2p, 2p+1}
            uint32_t bh[4][2], bl[4][2];
            #pragma unroll
            for (int p = 0; p < 2; p++) {
                int row = warpN*32 + (2*p + (lt >> 1))*8 + rt;
                int cw  = kt*8 + (lt & 1)*4;
                ldsm_x4(bh[2*p][0], bh[2*p][1], bh[2*p+1][0], bh[2*p+1][1],
                        &Wh32[row*20 + cw]);
                ldsm_x4(bl[2*p][0], bl[2*p][1], bl[2*p+1][0], bl[2*p+1][1],
                        &Wl32[row*20 + cw]);
            }
            #pragma unroll
            for (int mt = 0; mt < 4; mt++)
                #pragma unroll
                for (int nt = 0; nt < 4; nt++) {
                    mma_bf16(acc[mt][nt], ah[mt][0], ah[mt][1], ah[mt][2], ah[mt][3],
                             bh[nt][0], bh[nt][1]);
                    mma_bf16(acc[mt][nt], ah[mt][0], ah[mt][1], ah[mt][2], ah[mt][3],
                             bl[nt][0], bl[nt][1]);
                    mma_bf16(acc[mt][nt], al[mt][0], al[mt][1], al[mt][2], al[mt][3],
                             bh[nt][0], bh[nt][1]);
                }
        }
    }

    if (MODE == 0) {
        float* out = (float*)outA;
        #pragma unroll
        for (int mt = 0; mt < 4; mt++) {
            int m = m0 + warpM*64 + mt*16 + lr;
            #pragma unroll
            for (int nt = 0; nt < 4; nt++) {
                int n = n0 + warpN*32 + nt*8 + 2*c;
                float b0v = __ldg(&bias[n]);
                float b1v = __ldg(&bias[n+1]);
                *(float2*)&out[(size_t)m*BDIM + n] =
                    make_float2(acc[mt][nt][0] + b0v, acc[mt][nt][1] + b1v);
                *(float2*)&out[(size_t)(m+8)*BDIM + n] =
                    make_float2(acc[mt][nt][2] + b0v, acc[mt][nt][3] + b1v);
            }
        }
    } else {
        uint32_t* outh = (uint32_t*)outA;
        uint32_t* outl = (uint32_t*)outB;
        const int seg  = warpN & 1;
        const int head = (n0 + warpN*32) >> 6;
        #pragma unroll
        for (int mt = 0; mt < 4; mt++) {
            int m = m0 + warpM*64 + mt*16 + lr;
            int b = m / NSEQ;                 // tile never crosses batch
            int nseq = m - b*NSEQ;
            #pragma unroll
            for (int rh = 0; rh < 2; rh++) {
                int tok = nseq + rh*8;
                float vrot[4][2];
                if (MODE == 2) {
                    float pos = seg ? (float)(tok % HPATCH) : (float)(tok / HPATCH);
                    #pragma unroll
                    for (int nt01 = 0; nt01 < 2; nt01++)
                        #pragma unroll
                        for (int e = 0; e < 2; e++) {
                            int j = nt01*8 + 2*c + e;       // 0..15
                            float freq = powf(10000.0f, -(float)j / 16.0f);
                            float ang  = pos * freq;
                            float cc = cosf(ang);
                            float ss = sinf(ang);
                            int n1 = n0 + warpN*32 + j;
                            float x1 = acc[mt][nt01][e + 2*rh]   + __ldg(&bias[n1]);
                            float x2 = acc[mt][nt01+2][e + 2*rh] + __ldg(&bias[n1+16]);
                            vrot[nt01][e]   = x1*cc - x2*ss;
                            vrot[nt01+2][e] = x1*ss + x2*cc;
                        }
                } else {
                    #pragma unroll
                    for (int nt = 0; nt < 4; nt++) {
                        int n = n0 + warpN*32 + nt*8 + 2*c;
                        vrot[nt][0] = acc[mt][nt][0 + 2*rh] + __ldg(&bias[n]);
                        vrot[nt][1] = acc[mt][nt][1 + 2*rh] + __ldg(&bias[n+1]);
                    }
                }
                size_t rowbase = (((size_t)(b*NH + head))*NSEQ + tok)*32
                               + (size_t)seg*16;
                #pragma unroll
                for (int nt = 0; nt < 4; nt++) {
                    outh[rowbase + nt*4 + c] = pack2(vrot[nt][0], vrot[nt][1]);
                    outl[rowbase + nt*4 + c] = pack2(lo_of(vrot[nt][0]),
                                                     lo_of(vrot[nt][1]));
                }
            }
        }
    }
}

// =============================================================================
// Flash attention (bf16x3 mma, ldmatrix fragments). VERBATIM round 16.
// =============================================================================
#define FW 36            // row stride in words
#define QSC  0.18033688011112042f   // 0.125 * log2(e)
#define FL_SMEM (18432*4)

__global__ __launch_bounds__(256, 2)
void flash_kernel()
{
    extern __shared__ uint32_t dsm[];
    uint32_t* Qh32  = dsm;
    uint32_t* Ql32  = dsm + 4608;
    uint32_t* Ksh32 = dsm + 9216;
    uint32_t* Ksl32 = dsm + 11520;
    uint32_t* Vsh32 = dsm + 13824;
    uint32_t* Vsl32 = dsm + 16128;

    const int tid  = threadIdx.x;
    const int lane = tid & 31;
    const int wid  = tid >> 5;
    const int c    = lane & 3;
    const int lr   = lane >> 2;
    const int q0   = blockIdx.x * 128;
    const int bh   = blockIdx.y;

    const int lt  = lane >> 3;        // tile id
    const int rt  = lane & 7;         // row within tile

    const uint4* qhp = (const uint4*)(g_qh + (size_t)bh*NSEQ*32);
    const uint4* qlp = (const uint4*)(g_ql + (size_t)bh*NSEQ*32);
    const uint4* khp = (const uint4*)(g_kh + (size_t)bh*NSEQ*32);
    const uint4* klp = (const uint4*)(g_kl + (size_t)bh*NSEQ*32);
    const uint4* vhp = (const uint4*)(g_vh + (size_t)bh*NSEQ*32);
    const uint4* vlp = (const uint4*)(g_vl + (size_t)bh*NSEQ*32);

    // ---- stage Q once
    #pragma unroll
    for (int s = 0; s < 4; s++) {
        int idx = tid + s*256;                 // 0..1023 uint4 ids (128 x 8)
        int r   = idx >> 3;
        int qq  = idx & 7;
        *(uint4*)&Qh32[r*FW + qq*4] = qhp[(size_t)(q0+r)*8 + qq];
        *(uint4*)&Ql32[r*FW + qq*4] = qlp[(size_t)(q0+r)*8 + qq];
    }
    __syncthreads();

    float m0r = -__int_as_float(0x7f800000), m1r = m0r;   // -inf (log2 units)
    float l0 = 0.f, l1 = 0.f;
    float O[8][4];
    #pragma unroll
    for (int dt = 0; dt < 8; dt++)
        #pragma unroll
        for (int j = 0; j < 4; j++) O[dt][j] = 0.f;

    for (int kv0 = 0; kv0 < NSEQ; kv0 += 64) {
        // ---- K and V: straight packed uint4 copies (row-major)
        #pragma unroll
        for (int s = 0; s < 2; s++) {
            int idx = tid + s*256;             // 0..511 uint4 ids (64 x 8)
            int kv  = idx >> 3;
            int qq  = idx & 7;
            *(uint4*)&Ksh32[kv*FW + qq*4] = khp[(size_t)(kv0+kv)*8 + qq];
            *(uint4*)&Ksl32[kv*FW + qq*4] = klp[(size_t)(kv0+kv)*8 + qq];
            *(uint4*)&Vsh32[kv*FW + qq*4] = vhp[(size_t)(kv0+kv)*8 + qq];
            *(uint4*)&Vsl32[kv*FW + qq*4] = vlp[(size_t)(kv0+kv)*8 + qq];
        }
        __syncthreads();

        // ---- S = Q K^T (bf16x3), fp32 accum
        float sacc[8][4];
        #pragma unroll
        for (int nt = 0; nt < 8; nt++)
            #pragma unroll
            for (int j = 0; j < 4; j++) sacc[nt][j] = 0.f;

        #pragma unroll
        for (int kt = 0; kt < 4; kt++) {
            uint32_t qh0, qh1, qh2, qh3, ql0, ql1, ql2, ql3;
            {
                int row = wid*16 + (lt & 1)*8 + rt;
                int cw  = kt*8 + (lt >> 1)*4;
                ldsm_x4(qh0, qh1, qh2, qh3, &Qh32[row*FW + cw]);
                ldsm_x4(ql0, ql1, ql2, ql3, &Ql32[row*FW + cw]);
            }
            #pragma unroll
            for (int p = 0; p < 4; p++) {
                int row = (2*p + (lt >> 1))*8 + rt;
                int cw  = kt*8 + (lt & 1)*4;
                uint32_t kb0, kb1, kb2, kb3, lb0, lb1, lb2, lb3;
                ldsm_x4(kb0, kb1, kb2, kb3, &Ksh32[row*FW + cw]);
                ldsm_x4(lb0, lb1, lb2, lb3, &Ksl32[row*FW + cw]);
                mma_bf16(sacc[2*p],   qh0, qh1, qh2, qh3, kb0, kb1);
                mma_bf16(sacc[2*p],   qh0, qh1, qh2, qh3, lb0, lb1);
                mma_bf16(sacc[2*p],   ql0, ql1, ql2, ql3, kb0, kb1);
                mma_bf16(sacc[2*p+1], qh0, qh1, qh2, qh3, kb2, kb3);
                mma_bf16(sacc[2*p+1], qh0, qh1, qh2, qh3, lb2, lb3);
                mma_bf16(sacc[2*p+1], ql0, ql1, ql2, ql3, kb2, kb3);
            }
        }

        // ---- scale to log2 units
        #pragma unroll
        for (int nt = 0; nt < 8; nt++)
            #pragma unroll
            for (int j = 0; j < 4; j++) sacc[nt][j] *= QSC;

        // ---- online softmax (rows r=lr and r+8; quad = lanes sharing lr)
        float mx0 = -__int_as_float(0x7f800000), mx1 = mx0;
        #pragma unroll
        for (int nt = 0; nt < 8; nt++) {
            mx0 = fmaxf(mx0, fmaxf(sacc[nt][0], sacc[nt][1]));
            mx1 = fmaxf(mx1, fmaxf(sacc[nt][2], sacc[nt][3]));
        }
        mx0 = fmaxf(mx0, __shfl_xor_sync(0xffffffffu, mx0, 1));
        mx0 = fmaxf(mx0, __shfl_xor_sync(0xffffffffu, mx0, 2));
        mx1 = fmaxf(mx1, __shfl_xor_sync(0xffffffffu, mx1, 1));
        mx1 = fmaxf(mx1, __shfl_xor_sync(0xffffffffu, mx1, 2));

        float mn0 = fmaxf(m0r, mx0);
        float mn1 = fmaxf(m1r, mx1);
        float cr0 = ex2_approx(m0r - mn0);
        float cr1 = ex2_approx(m1r - mn1);
        m0r = mn0; m1r = mn1;

        float rs0 = 0.f, rs1 = 0.f;
        #pragma unroll
        for (int nt = 0; nt < 8; nt++) {
            sacc[nt][0] = ex2_approx(sacc[nt][0] - mn0);
            sacc[nt][1] = ex2_approx(sacc[nt][1] - mn0);
            sacc[nt][2] = ex2_approx(sacc[nt][2] - mn1);
            sacc[nt][3] = ex2_approx(sacc[nt][3] - mn1);
            rs0 += sacc[nt][0] + sacc[nt][1];
            rs1 += sacc[nt][2] + sacc[nt][3];
        }
        rs0 += __shfl_xor_sync(0xffffffffu, rs0, 1);
        rs0 += __shfl_xor_sync(0xffffffffu, rs0, 2);
        rs1 += __shfl_xor_sync(0xffffffffu, rs1, 1);
        rs1 += __shfl_xor_sync(0xffffffffu, rs1, 2);
        l0 = l0 * cr0 + rs0;
        l1 = l1 * cr1 + rs1;

        #pragma unroll
        for (int dt = 0; dt < 8; dt++) {
            O[dt][0] *= cr0; O[dt][1] *= cr0;
            O[dt][2] *= cr1; O[dt][3] *= cr1;
        }

        // ---- O += P V (bf16x3); P from registers; V B-frags via ldmatrix.trans
        #pragma unroll
        for (int kt = 0; kt < 4; kt++) {
            uint32_t pa[4], pl[4];
            pa[0] = pack2(sacc[2*kt][0],   sacc[2*kt][1]);
            pa[1] = pack2(sacc[2*kt][2],   sacc[2*kt][3]);
            pa[2] = pack2(sacc[2*kt+1][0], sacc[2*kt+1][1]);
            pa[3] = pack2(sacc[2*kt+1][2], sacc[2*kt+1][3]);
            pl[0] = pack2(lo_of(sacc[2*kt][0]),   lo_of(sacc[2*kt][1]));
            pl[1] = pack2(lo_of(sacc[2*kt][2]),   lo_of(sacc[2*kt][3]));
            pl[2] = pack2(lo_of(sacc[2*kt+1][0]), lo_of(sacc[2*kt+1][1]));
            pl[3] = pack2(lo_of(sacc[2*kt+1][2]), lo_of(sacc[2*kt+1][3]));
            #pragma unroll
            for (int p = 0; p < 4; p++) {
                int row = kt*16 + (lt & 1)*8 + rt;
                int cw  = (2*p + (lt >> 1))*4;
                uint32_t vb0, vb1, vb2, vb3, wl0, wl1, wl2, wl3;
                ldsm_x4_t(vb0, vb1, vb2, vb3, &Vsh32[row*FW + cw]);
                ldsm_x4_t(wl0, wl1, wl2, wl3, &Vsl32[row*FW + cw]);
                mma_bf16(O[2*p],   pa[0], pa[1], pa[2], pa[3], vb0, vb1);
                mma_bf16(O[2*p],   pa[0], pa[1], pa[2], pa[3], wl0, wl1);
                mma_bf16(O[2*p],   pl[0], pl[1], pl[2], pl[3], vb0, vb1);
                mma_bf16(O[2*p+1], pa[0], pa[1], pa[2], pa[3], vb2, vb3);
                mma_bf16(O[2*p+1], pa[0], pa[1], pa[2], pa[3], wl2, wl3);
                mma_bf16(O[2*p+1], pl[0], pl[1], pl[2], pl[3], vb2, vb3);
            }
        }
        __syncthreads();
    }

    // ---- finalize: /= l, write to g_attn [b, n, h*64 + d]
    const int b = bh >> 4;
    const int h = bh & 15;
    float inv0 = 1.0f / l0;
    float inv1 = 1.0f / l1;
    int row0 = q0 + wid*16 + lr;
    #pragma unroll
    for (int dt = 0; dt < 8; dt++) {
        int d = dt*8 + 2*c;
        size_t r0 = ((size_t)(b*NSEQ + row0))*BDIM + h*HD + d;
        *(float2*)&g_attn[r0]           = make_float2(O[dt][0]*inv0, O[dt][1]*inv0);
        *(float2*)&g_attn[r0 + 8*BDIM]  = make_float2(O[dt][2]*inv1, O[dt][3]*inv1);
    }
}

// =============================================================================
// Launch. Binding: size-classified (order-robust, verified in round 4).
// =============================================================================
extern "C" void kernel_launch(void* const* d_in, const int* in_sizes, int n_in,
                              void* d_out, int out_size)
{
    const float* big[3]  = {0,0,0};
    const float* Ws[4]   = {0,0,0,0};
    const float* bs[4]   = {0,0,0,0};
    int nbig = 0, nW = 0, nb = 0;
    for (int i = 0; i < n_in; i++) {
        int s = in_sizes[i];
        if (s == MROWS*BDIM)      { if (nbig < 3) big[nbig++] = (const float*)d_in[i]; }
        else if (s == BDIM*BDIM)  { if (nW  < 4) Ws[nW++]   = (const float*)d_in[i]; }
        else if (s == BDIM)       { if (nb  < 4) bs[nb++]   = (const float*)d_in[i]; }
    }
    const float* query = big[0];
    const float* key   = big[1];
    const float* value = big[2];
    const float* Wq = Ws[0]; const float* bq = bs[0];
    const float* Wk = Ws[1]; const float* bk = bs[1];
    const float* Wv = Ws[2]; const float* bv = bs[2];
    const float* Wo = Ws[3]; const float* bo = bs[3];

    void *qh, *ql, *kh, *kl, *vh, *vl;
    float* ab;
    cudaGetSymbolAddress(&qh, g_qh);
    cudaGetSymbolAddress(&ql, g_ql);
    cudaGetSymbolAddress(&kh, g_kh);
    cudaGetSymbolAddress(&kl, g_kl);
    cudaGetSymbolAddress(&vh, g_vh);
    cudaGetSymbolAddress(&vl, g_vl);
    cudaGetSymbolAddress((void**)&ab, g_attn);

    cudaFuncSetAttribute(flash_kernel,
                         cudaFuncAttributeMaxDynamicSharedMemorySize, FL_SMEM);

    dim3 pg(BDIM/128, MROWS/128);   // (8, 72)
    proj_mma3<2><<<pg, 256>>>(query, Wq, bq, qh, ql);    // Q: rope + packed
    proj_mma3<2><<<pg, 256>>>(key,   Wk, bk, kh, kl);    // K: rope + packed
    proj_mma3<3><<<pg, 256>>>(value, Wv, bv, vh, vl);    // V: packed

    flash_kernel<<<dim3(NSEQ/128, NB*NH), 256, FL_SMEM>>>();

    proj_mma3<0><<<pg, 256>>>(ab, Wo, bo, d_out, nullptr);
}